// round 2
// baseline (speedup 1.0000x reference)
#include <cuda_runtime.h>
#include <cuda_bf16.h>

#define N_NODES 10000
#define N_EDGES 100000
#define DIN 64
#define H 64
#define EIN 16
#define EH 128
#define STEPS 3

// ---------------- device scratch (no allocations allowed) ----------------
__device__ float g_x[N_NODES * H];        // current node features
__device__ float g_agg[N_NODES * H];      // per-step aggregation buffer
__device__ float g_h1[N_EDGES * EH];      // edge hidden layer
__device__ float g_wedge[(size_t)N_EDGES * H * H];  // 1.64 GB per-edge HxH weights
__device__ float g_sum[H];
__device__ float g_sumsq[H];

// ---------------- node MLP: out = relu(n_feat @ W0 + b0) ----------------
__global__ void node_mlp(const float* __restrict__ nf, const float* __restrict__ W0,
                         const float* __restrict__ b0) {
    int n = blockIdx.x;
    int h = threadIdx.x;  // 64 threads
    __shared__ float xs[DIN];
    xs[h] = nf[n * DIN + h];
    __syncthreads();
    float acc = b0[h];
#pragma unroll
    for (int i = 0; i < DIN; i++) acc += xs[i] * W0[i * H + h];
    g_x[n * H + h] = fmaxf(acc, 0.0f);
}

// ---------------- edge hidden: h1 = relu(e_feat @ We1 + be1) ----------------
__global__ void edge_h1(const float* __restrict__ ef, const float* __restrict__ We1,
                        const float* __restrict__ be1) {
    int gid = blockIdx.x * blockDim.x + threadIdx.x;  // covers E*EH
    int e = gid >> 7;
    int k = gid & 127;
    if (e >= N_EDGES) return;
    float acc = be1[k];
#pragma unroll
    for (int i = 0; i < EIN; i++) acc += ef[e * EIN + i] * We1[i * EH + k];
    g_h1[gid] = fmaxf(acc, 0.0f);
}

// ---------------- big GEMM: w_edge[e, j] = h1[e,:] @ We2[:, j] + be2[j] ----------------
// [E x 4096] = [E x 128] @ [128 x 4096], fp32 register-tiled
#define BM 128
#define BN 64
#define BK 16
__global__ __launch_bounds__(256) void wedge_gemm(const float* __restrict__ We2,
                                                  const float* __restrict__ be2) {
    __shared__ float As[BK][BM];  // transposed A tile
    __shared__ float Bs[BK][BN];

    int t = threadIdx.x;
    int block_m = blockIdx.y * BM;  // edge base
    int block_n = blockIdx.x * BN;  // column base
    int tx = t & 15;                // n-group: 4 cols
    int ty = t >> 4;                // m-group: 8 rows

    float acc[8][4];
#pragma unroll
    for (int i = 0; i < 8; i++)
#pragma unroll
        for (int j = 0; j < 4; j++) acc[i][j] = 0.0f;

    for (int kt = 0; kt < EH; kt += BK) {
        // load A tile: 128 rows x 16 k  (2 float4 per thread), store transposed
#pragma unroll
        for (int l = 0; l < 2; l++) {
            int v = t + l * 256;      // 0..511
            int r = v >> 2;           // 0..127
            int c = (v & 3) * 4;      // 0,4,8,12
            int e = block_m + r;
            float4 av = make_float4(0.f, 0.f, 0.f, 0.f);
            if (e < N_EDGES) av = *(const float4*)(g_h1 + (size_t)e * EH + kt + c);
            As[c + 0][r] = av.x;
            As[c + 1][r] = av.y;
            As[c + 2][r] = av.z;
            As[c + 3][r] = av.w;
        }
        // load B tile: 16 k x 64 cols (1 float4 per thread)
        {
            int r = t >> 4;           // 0..15
            int c = (t & 15) * 4;
            float4 bv = *(const float4*)(We2 + (size_t)(kt + r) * 4096 + block_n + c);
            *(float4*)&Bs[r][c] = bv;
        }
        __syncthreads();
#pragma unroll
        for (int k = 0; k < BK; k++) {
            float4 a0 = *(float4*)&As[k][ty * 8];
            float4 a1 = *(float4*)&As[k][ty * 8 + 4];
            float4 bv = *(float4*)&Bs[k][tx * 4];
            float a[8] = {a0.x, a0.y, a0.z, a0.w, a1.x, a1.y, a1.z, a1.w};
            float b[4] = {bv.x, bv.y, bv.z, bv.w};
#pragma unroll
            for (int i = 0; i < 8; i++)
#pragma unroll
                for (int j = 0; j < 4; j++) acc[i][j] += a[i] * b[j];
        }
        __syncthreads();
    }

    float4 bias = *(const float4*)(be2 + block_n + tx * 4);
#pragma unroll
    for (int i = 0; i < 8; i++) {
        int e = block_m + ty * 8 + i;
        if (e < N_EDGES) {
            float4 v = make_float4(acc[i][0] + bias.x, acc[i][1] + bias.y,
                                   acc[i][2] + bias.z, acc[i][3] + bias.w);
            *(float4*)(g_wedge + (size_t)e * 4096 + block_n + tx * 4) = v;
        }
    }
}

// ---------------- init agg with conv_bias ----------------
__global__ void init_agg(const float* __restrict__ conv_bias) {
    int i = blockIdx.x * blockDim.x + threadIdx.x;
    if (i < N_NODES * H) g_agg[i] = conv_bias[i & 63];
}

// ---------------- message + scatter: warp per edge ----------------
__global__ void msg_kernel(const int* __restrict__ src, const int* __restrict__ dst) {
    int widx = (blockIdx.x * blockDim.x + threadIdx.x) >> 5;
    int lane = threadIdx.x & 31;
    if (widx >= N_EDGES) return;
    int s = src[widx];
    int d = dst[widx];
    float x0 = g_x[s * H + lane];
    float x1 = g_x[s * H + 32 + lane];
    const float2* w2 = (const float2*)(g_wedge + (size_t)widx * H * H);
    float m0 = 0.f, m1 = 0.f;  // outputs o = 2*lane, 2*lane+1
#pragma unroll 8
    for (int i = 0; i < 32; i++) {
        float xi = __shfl_sync(0xffffffffu, x0, i);
        float2 wv = w2[i * 32 + lane];
        m0 += xi * wv.x;
        m1 += xi * wv.y;
    }
#pragma unroll 8
    for (int i = 0; i < 32; i++) {
        float xi = __shfl_sync(0xffffffffu, x1, i);
        float2 wv = w2[(i + 32) * 32 + lane];
        m0 += xi * wv.x;
        m1 += xi * wv.y;
    }
    atomicAdd(&g_agg[d * H + 2 * lane], m0);
    atomicAdd(&g_agg[d * H + 2 * lane + 1], m1);
}

// ---------------- relu of agg into x ----------------
__global__ void relu_step() {
    int i = blockIdx.x * blockDim.x + threadIdx.x;
    if (i < N_NODES * H) g_x[i] = fmaxf(g_agg[i], 0.0f);
}

// ---------------- BatchNorm ----------------
__global__ void bn_zero() {
    int t = threadIdx.x;
    if (t < H) {
        g_sum[t] = 0.f;
        g_sumsq[t] = 0.f;
    }
}

__global__ void bn_reduce() {
    int t = threadIdx.x;
    int h = t & 63;
    int rsub = t >> 6;
    float s = 0.f, q = 0.f;
    for (int r = blockIdx.x * 4 + rsub; r < N_NODES; r += gridDim.x * 4) {
        float v = g_x[r * H + h];
        s += v;
        q += v * v;
    }
    __shared__ float ss[256], sq[256];
    ss[t] = s;
    sq[t] = q;
    __syncthreads();
    if (t < 64) {
        s = ss[t] + ss[t + 64] + ss[t + 128] + ss[t + 192];
        q = sq[t] + sq[t + 64] + sq[t + 128] + sq[t + 192];
        atomicAdd(&g_sum[h], s);
        atomicAdd(&g_sumsq[h], q);
    }
}

__global__ void bn_apply(const float* __restrict__ gamma, const float* __restrict__ beta,
                         float* __restrict__ out) {
    int i = blockIdx.x * blockDim.x + threadIdx.x;
    if (i >= N_NODES * H) return;
    int h = i & 63;
    float mean = g_sum[h] / (float)N_NODES;
    float var = g_sumsq[h] / (float)N_NODES - mean * mean;
    out[i] = (g_x[i] - mean) * rsqrtf(var + 1e-5f) * gamma[h] + beta[h];
}

// ---------------- launch ----------------
extern "C" void kernel_launch(void* const* d_in, const int* in_sizes, int n_in,
                              void* d_out, int out_size) {
    const float* n_feat    = (const float*)d_in[0];
    const float* e_feat    = (const float*)d_in[1];
    const int*   src       = (const int*)d_in[2];
    const int*   dst       = (const int*)d_in[3];
    const float* W0        = (const float*)d_in[4];
    const float* b0        = (const float*)d_in[5];
    const float* We1       = (const float*)d_in[6];
    const float* be1       = (const float*)d_in[7];
    const float* We2       = (const float*)d_in[8];
    const float* be2       = (const float*)d_in[9];
    const float* conv_bias = (const float*)d_in[10];
    const float* gamma     = (const float*)d_in[11];
    const float* beta      = (const float*)d_in[12];
    float* out = (float*)d_out;

    // node MLP
    node_mlp<<<N_NODES, 64>>>(n_feat, W0, b0);
    // edge hidden
    edge_h1<<<(N_EDGES * EH) / 256, 256>>>(e_feat, We1, be1);
    // big GEMM: per-edge HxH weights (step-invariant, computed once)
    dim3 ggrid(4096 / BN, (N_EDGES + BM - 1) / BM);
    wedge_gemm<<<ggrid, 256>>>(We2, be2);

    int nh = N_NODES * H;
    int eb = (N_EDGES * 32 + 255) / 256;  // warp per edge
    for (int step = 0; step < STEPS; step++) {
        init_agg<<<(nh + 255) / 256, 256>>>(conv_bias);
        msg_kernel<<<eb, 256>>>(src, dst);
        relu_step<<<(nh + 255) / 256, 256>>>();
    }

    bn_zero<<<1, 64>>>();
    bn_reduce<<<100, 256>>>();
    bn_apply<<<(nh + 255) / 256, 256>>>(gamma, beta, out);
    (void)in_sizes; (void)n_in; (void)out_size;
}

// round 4
// speedup vs baseline: 1.2307x; 1.2307x over previous
#include <cuda_runtime.h>
#include <cuda_bf16.h>
#include <cstdint>

#define N_NODES 10000
#define N_EDGES 100000
#define DIN 64
#define H 64
#define EIN 16
#define EH 128
#define STEPS 3

// ---------------- device scratch ----------------
__device__ float g_x[N_NODES * H];
__device__ float g_agg[N_NODES * H];
__device__ __nv_bfloat16 g_h1h[N_EDGES * EH];   // h1 split hi
__device__ __nv_bfloat16 g_h1l[N_EDGES * EH];   // h1 split lo
__device__ __nv_bfloat16 g_We2h[4096 * EH];     // We2^T split hi  [n][k]
__device__ __nv_bfloat16 g_We2l[4096 * EH];     // We2^T split lo
__device__ float g_wedge[(size_t)N_EDGES * H * H];  // 1.64 GB fp32
__device__ float g_sum[H];
__device__ float g_sumsq[H];

// ---------------- node MLP ----------------
__global__ void node_mlp(const float* __restrict__ nf, const float* __restrict__ W0,
                         const float* __restrict__ b0) {
    int n = blockIdx.x;
    int h = threadIdx.x;
    __shared__ float xs[DIN];
    xs[h] = nf[n * DIN + h];
    __syncthreads();
    float acc = b0[h];
#pragma unroll
    for (int i = 0; i < DIN; i++) acc += xs[i] * W0[i * H + h];
    g_x[n * H + h] = fmaxf(acc, 0.0f);
}

// ---------------- edge hidden: h1 = relu(e_feat @ We1 + be1), bf16 split ----------------
__global__ void edge_h1(const float* __restrict__ ef, const float* __restrict__ We1,
                        const float* __restrict__ be1) {
    int gid = blockIdx.x * blockDim.x + threadIdx.x;
    int e = gid >> 7;
    int k = gid & 127;
    if (e >= N_EDGES) return;
    float acc = be1[k];
#pragma unroll
    for (int i = 0; i < EIN; i++) acc += ef[e * EIN + i] * We1[i * EH + k];
    float v = fmaxf(acc, 0.0f);
    __nv_bfloat16 hi = __float2bfloat16(v);
    __nv_bfloat16 lo = __float2bfloat16(v - __bfloat162float(hi));
    g_h1h[gid] = hi;
    g_h1l[gid] = lo;
}

// ---------------- We2 transpose + bf16 split: [k,n] -> [n,k] ----------------
__global__ void we2_prep(const float* __restrict__ We2) {
    int idx = blockIdx.x * blockDim.x + threadIdx.x;  // 4096*128
    if (idx >= 4096 * EH) return;
    int n = idx >> 7;
    int k = idx & 127;
    float v = We2[k * 4096 + n];
    __nv_bfloat16 hi = __float2bfloat16(v);
    __nv_bfloat16 lo = __float2bfloat16(v - __bfloat162float(hi));
    g_We2h[idx] = hi;
    g_We2l[idx] = lo;
}

// ---------------- mma.sync bf16-split GEMM: w_edge = h1 @ We2 + be2 ----------------
// CTA tile: 128(M edges) x 128(N cols), K=128 resident. 3 split passes into fp32 regs.
// smem rows padded to 136 bf16 (272B) -> ldmatrix conflict-free.
#define SROW 136
#define A_HI_OFF 0
#define A_LO_OFF (128 * SROW * 2)
#define B_HI_OFF (2 * 128 * SROW * 2)
#define B_LO_OFF (3 * 128 * SROW * 2)
#define WSMEM_TOTAL (4 * 128 * SROW * 2)

__device__ __forceinline__ uint32_t smem_u32(const void* p) {
    uint32_t a;
    asm("{ .reg .u64 t; cvta.to.shared.u64 t, %1; cvt.u32.u64 %0, t; }" : "=r"(a) : "l"(p));
    return a;
}

__device__ __forceinline__ void ldsm_x4(uint32_t& r0, uint32_t& r1, uint32_t& r2,
                                        uint32_t& r3, uint32_t addr) {
    asm volatile("ldmatrix.sync.aligned.m8n8.x4.shared.b16 {%0,%1,%2,%3}, [%4];"
                 : "=r"(r0), "=r"(r1), "=r"(r2), "=r"(r3) : "r"(addr));
}

__device__ __forceinline__ void mma_bf16(float& c0, float& c1, float& c2, float& c3,
                                         uint32_t a0, uint32_t a1, uint32_t a2, uint32_t a3,
                                         uint32_t b0, uint32_t b1) {
    asm volatile(
        "mma.sync.aligned.m16n8k16.row.col.f32.bf16.bf16.f32 "
        "{%0,%1,%2,%3}, {%4,%5,%6,%7}, {%8,%9}, {%0,%1,%2,%3};"
        : "+f"(c0), "+f"(c1), "+f"(c2), "+f"(c3)
        : "r"(a0), "r"(a1), "r"(a2), "r"(a3), "r"(b0), "r"(b1));
}

__global__ void __launch_bounds__(256) wedge_gemm_mma(const float* __restrict__ be2) {
    extern __shared__ char smem[];
    const uint32_t sbase = smem_u32(smem);
    const int tid = threadIdx.x;
    const int wid = tid >> 5;
    const int lane = tid & 31;
    const int block_n = blockIdx.x * 128;
    const int block_m = blockIdx.y * 128;

    // ---- stage A (hi+lo) and B (hi+lo) tiles into smem ----
    // A: 128 rows x 128 bf16; 2048 uint4 per buffer; 8 per thread
    for (int i = tid; i < 2048; i += 256) {
        int r = i >> 4;
        int c = (i & 15) * 8;  // bf16 col
        int e = block_m + r;
        uint4 vh = make_uint4(0, 0, 0, 0), vl = make_uint4(0, 0, 0, 0);
        if (e < N_EDGES) {
            vh = *(const uint4*)(g_h1h + (size_t)e * EH + c);
            vl = *(const uint4*)(g_h1l + (size_t)e * EH + c);
        }
        *(uint4*)(smem + A_HI_OFF + r * (SROW * 2) + c * 2) = vh;
        *(uint4*)(smem + A_LO_OFF + r * (SROW * 2) + c * 2) = vl;
    }
    // B: 128 n-rows x 128 k
    for (int i = tid; i < 2048; i += 256) {
        int r = i >> 4;
        int c = (i & 15) * 8;
        int n = block_n + r;
        uint4 vh = *(const uint4*)(g_We2h + (size_t)n * EH + c);
        uint4 vl = *(const uint4*)(g_We2l + (size_t)n * EH + c);
        *(uint4*)(smem + B_HI_OFF + r * (SROW * 2) + c * 2) = vh;
        *(uint4*)(smem + B_LO_OFF + r * (SROW * 2) + c * 2) = vl;
    }
    __syncthreads();

    // ---- warp tiling: 4 warps along M, 2 along N; warp tile 32(M) x 64(N) ----
    const int wm = wid & 3;        // 0..3
    const int wn = wid >> 2;       // 0..1
    const int m_off = wm * 32;
    const int n_off = wn * 64;

    float acc[2][8][4];
#pragma unroll
    for (int mt = 0; mt < 2; mt++)
#pragma unroll
        for (int nt = 0; nt < 8; nt++)
#pragma unroll
            for (int q = 0; q < 4; q++) acc[mt][nt][q] = 0.0f;

    const uint32_t a_bufs[3] = {sbase + A_HI_OFF, sbase + A_HI_OFF, sbase + A_LO_OFF};
    const uint32_t b_bufs[3] = {sbase + B_HI_OFF, sbase + B_LO_OFF, sbase + B_HI_OFF};

    // precomputed lane pieces
    const int a_row_l = lane & 15;            // row within 16
    const int a_koff = (lane >> 4) << 3;      // 0 or 8
    const int b_row_l = ((lane >> 4) << 3) + (lane & 7);  // row within 16 (two n-tiles)
    const int b_koff = ((lane >> 3) & 1) << 3;            // 0 or 8

#pragma unroll
    for (int p = 0; p < 3; p++) {
        const uint32_t Ab = a_bufs[p];
        const uint32_t Bb = b_bufs[p];
#pragma unroll
        for (int ks = 0; ks < 8; ks++) {
            const int kb = ks * 16;
            uint32_t a[2][4];
#pragma unroll
            for (int mt = 0; mt < 2; mt++) {
                uint32_t addr = Ab + (uint32_t)((m_off + mt * 16 + a_row_l) * (SROW * 2) +
                                                (kb + a_koff) * 2);
                ldsm_x4(a[mt][0], a[mt][1], a[mt][2], a[mt][3], addr);
            }
            uint32_t b[8][2];
#pragma unroll
            for (int np = 0; np < 4; np++) {  // pairs of n-tiles
                uint32_t addr = Bb + (uint32_t)((n_off + np * 16 + b_row_l) * (SROW * 2) +
                                                (kb + b_koff) * 2);
                uint32_t r0, r1, r2, r3;
                ldsm_x4(r0, r1, r2, r3, addr);
                b[np * 2][0] = r0; b[np * 2][1] = r1;
                b[np * 2 + 1][0] = r2; b[np * 2 + 1][1] = r3;
            }
#pragma unroll
            for (int mt = 0; mt < 2; mt++)
#pragma unroll
                for (int nt = 0; nt < 8; nt++)
                    mma_bf16(acc[mt][nt][0], acc[mt][nt][1], acc[mt][nt][2], acc[mt][nt][3],
                             a[mt][0], a[mt][1], a[mt][2], a[mt][3],
                             b[nt][0], b[nt][1]);
        }
    }

    // ---- epilogue: add bias, store fp32 ----
    const int qrow = lane >> 2;        // 0..7
    const int qcol = (lane & 3) * 2;   // 0,2,4,6
#pragma unroll
    for (int mt = 0; mt < 2; mt++) {
        int r0 = block_m + m_off + mt * 16 + qrow;
        int r1 = r0 + 8;
#pragma unroll
        for (int nt = 0; nt < 8; nt++) {
            int col = block_n + n_off + nt * 8 + qcol;
            float bx = be2[col];
            float by = be2[col + 1];
            if (r0 < N_EDGES) {
                float2 v0 = make_float2(acc[mt][nt][0] + bx, acc[mt][nt][1] + by);
                *(float2*)(g_wedge + (size_t)r0 * 4096 + col) = v0;
            }
            if (r1 < N_EDGES) {
                float2 v1 = make_float2(acc[mt][nt][2] + bx, acc[mt][nt][3] + by);
                *(float2*)(g_wedge + (size_t)r1 * 4096 + col) = v1;
            }
        }
    }
}

// ---------------- init agg with conv_bias ----------------
__global__ void init_agg(const float* __restrict__ conv_bias) {
    int i = blockIdx.x * blockDim.x + threadIdx.x;
    if (i < N_NODES * H) g_agg[i] = conv_bias[i & 63];
}

// ---------------- message + scatter: warp per edge ----------------
__global__ void msg_kernel(const int* __restrict__ src, const int* __restrict__ dst) {
    int widx = (blockIdx.x * blockDim.x + threadIdx.x) >> 5;
    int lane = threadIdx.x & 31;
    if (widx >= N_EDGES) return;
    int s = src[widx];
    int d = dst[widx];
    float x0 = g_x[s * H + lane];
    float x1 = g_x[s * H + 32 + lane];
    const float2* w2 = (const float2*)(g_wedge + (size_t)widx * H * H);
    float m0 = 0.f, m1 = 0.f;
#pragma unroll 8
    for (int i = 0; i < 32; i++) {
        float xi = __shfl_sync(0xffffffffu, x0, i);
        float2 wv = w2[i * 32 + lane];
        m0 += xi * wv.x;
        m1 += xi * wv.y;
    }
#pragma unroll 8
    for (int i = 0; i < 32; i++) {
        float xi = __shfl_sync(0xffffffffu, x1, i);
        float2 wv = w2[(i + 32) * 32 + lane];
        m0 += xi * wv.x;
        m1 += xi * wv.y;
    }
    atomicAdd(&g_agg[d * H + 2 * lane], m0);
    atomicAdd(&g_agg[d * H + 2 * lane + 1], m1);
}

// ---------------- relu step ----------------
__global__ void relu_step() {
    int i = blockIdx.x * blockDim.x + threadIdx.x;
    if (i < N_NODES * H) g_x[i] = fmaxf(g_agg[i], 0.0f);
}

// ---------------- BatchNorm ----------------
__global__ void bn_zero() {
    int t = threadIdx.x;
    if (t < H) {
        g_sum[t] = 0.f;
        g_sumsq[t] = 0.f;
    }
}

__global__ void bn_reduce() {
    int t = threadIdx.x;
    int h = t & 63;
    int rsub = t >> 6;
    float s = 0.f, q = 0.f;
    for (int r = blockIdx.x * 4 + rsub; r < N_NODES; r += gridDim.x * 4) {
        float v = g_x[r * H + h];
        s += v;
        q += v * v;
    }
    __shared__ float ss[256], sq[256];
    ss[t] = s;
    sq[t] = q;
    __syncthreads();
    if (t < 64) {
        s = ss[t] + ss[t + 64] + ss[t + 128] + ss[t + 192];
        q = sq[t] + sq[t + 64] + sq[t + 128] + sq[t + 192];
        atomicAdd(&g_sum[h], s);
        atomicAdd(&g_sumsq[h], q);
    }
}

__global__ void bn_apply(const float* __restrict__ gamma, const float* __restrict__ beta,
                         float* __restrict__ out) {
    int i = blockIdx.x * blockDim.x + threadIdx.x;
    if (i >= N_NODES * H) return;
    int h = i & 63;
    float mean = g_sum[h] / (float)N_NODES;
    float var = g_sumsq[h] / (float)N_NODES - mean * mean;
    out[i] = (g_x[i] - mean) * rsqrtf(var + 1e-5f) * gamma[h] + beta[h];
}

// ---------------- launch ----------------
extern "C" void kernel_launch(void* const* d_in, const int* in_sizes, int n_in,
                              void* d_out, int out_size) {
    const float* n_feat    = (const float*)d_in[0];
    const float* e_feat    = (const float*)d_in[1];
    const int*   src       = (const int*)d_in[2];
    const int*   dst       = (const int*)d_in[3];
    const float* W0        = (const float*)d_in[4];
    const float* b0        = (const float*)d_in[5];
    const float* We1       = (const float*)d_in[6];
    const float* be1       = (const float*)d_in[7];
    const float* We2       = (const float*)d_in[8];
    const float* be2       = (const float*)d_in[9];
    const float* conv_bias = (const float*)d_in[10];
    const float* gamma     = (const float*)d_in[11];
    const float* beta      = (const float*)d_in[12];
    float* out = (float*)d_out;

    cudaFuncSetAttribute(wedge_gemm_mma, cudaFuncAttributeMaxDynamicSharedMemorySize,
                         WSMEM_TOTAL);

    node_mlp<<<N_NODES, 64>>>(n_feat, W0, b0);
    edge_h1<<<(N_EDGES * EH) / 256, 256>>>(e_feat, We1, be1);
    we2_prep<<<(4096 * EH) / 256, 256>>>(We2);

    // x = N-blocks (fast-varying) so the A tile for a given M-block stays hot in L2
    dim3 ggrid(4096 / 128, (N_EDGES + 127) / 128);
    wedge_gemm_mma<<<ggrid, 256, WSMEM_TOTAL>>>(be2);

    int nh = N_NODES * H;
    int eb = (N_EDGES * 32 + 255) / 256;
    for (int step = 0; step < STEPS; step++) {
        init_agg<<<(nh + 255) / 256, 256>>>(conv_bias);
        msg_kernel<<<eb, 256>>>(src, dst);
        relu_step<<<(nh + 255) / 256, 256>>>();
    }

    bn_zero<<<1, 64>>>();
    bn_reduce<<<100, 256>>>();
    bn_apply<<<(nh + 255) / 256, 256>>>(gamma, beta, out);
    (void)in_sizes; (void)n_in; (void)out_size;
}

// round 5
// speedup vs baseline: 1.8665x; 1.5166x over previous
#include <cuda_runtime.h>
#include <cuda_bf16.h>
#include <cstdint>

#define N_NODES 10000
#define N_EDGES 100000
#define DIN 64
#define H 64
#define EIN 16
#define EH 128
#define STEPS 3
#define KC 384   // concatenated split K

// ---------------- device scratch ----------------
__device__ float g_x[N_NODES * H];
__device__ float g_agg[N_NODES * H];
__device__ __nv_bfloat16 g_h1c[(size_t)N_EDGES * KC];   // [hi | hi | lo]
__device__ __nv_bfloat16 g_We2c[4096 * KC];             // [hi | lo | hi] (row = out col n)
__device__ float g_wedge[(size_t)N_EDGES * H * H];      // 1.64 GB fp32
__device__ float g_sum[H];
__device__ float g_sumsq[H];

// ---------------- helpers ----------------
__device__ __forceinline__ uint32_t smem_u32(const void* p) {
    uint32_t a;
    asm("{ .reg .u64 t; cvta.to.shared.u64 t, %1; cvt.u32.u64 %0, t; }" : "=r"(a) : "l"(p));
    return a;
}
__device__ __forceinline__ void cp_async16(uint32_t dst, const void* src, int src_bytes) {
    asm volatile("cp.async.cg.shared.global [%0], [%1], 16, %2;"
                 :: "r"(dst), "l"(src), "r"(src_bytes));
}
#define CP_COMMIT() asm volatile("cp.async.commit_group;" ::: "memory")
#define CP_WAIT(n)  asm volatile("cp.async.wait_group %0;" :: "n"(n) : "memory")

__device__ __forceinline__ void ldsm_x4(uint32_t& r0, uint32_t& r1, uint32_t& r2,
                                        uint32_t& r3, uint32_t addr) {
    asm volatile("ldmatrix.sync.aligned.m8n8.x4.shared.b16 {%0,%1,%2,%3}, [%4];"
                 : "=r"(r0), "=r"(r1), "=r"(r2), "=r"(r3) : "r"(addr));
}
__device__ __forceinline__ void mma_bf16(float& c0, float& c1, float& c2, float& c3,
                                         uint32_t a0, uint32_t a1, uint32_t a2, uint32_t a3,
                                         uint32_t b0, uint32_t b1) {
    asm volatile(
        "mma.sync.aligned.m16n8k16.row.col.f32.bf16.bf16.f32 "
        "{%0,%1,%2,%3}, {%4,%5,%6,%7}, {%8,%9}, {%0,%1,%2,%3};"
        : "+f"(c0), "+f"(c1), "+f"(c2), "+f"(c3)
        : "r"(a0), "r"(a1), "r"(a2), "r"(a3), "r"(b0), "r"(b1));
}

// ---------------- node MLP ----------------
__global__ void node_mlp(const float* __restrict__ nf, const float* __restrict__ W0,
                         const float* __restrict__ b0) {
    int n = blockIdx.x;
    int h = threadIdx.x;
    __shared__ float xs[DIN];
    xs[h] = nf[n * DIN + h];
    __syncthreads();
    float acc = b0[h];
#pragma unroll
    for (int i = 0; i < DIN; i++) acc += xs[i] * W0[i * H + h];
    g_x[n * H + h] = fmaxf(acc, 0.0f);
}

// ---------------- edge hidden -> concatenated split [hi|hi|lo] ----------------
__global__ void edge_h1(const float* __restrict__ ef, const float* __restrict__ We1,
                        const float* __restrict__ be1) {
    int gid = blockIdx.x * blockDim.x + threadIdx.x;
    int e = gid >> 7;
    int k = gid & 127;
    if (e >= N_EDGES) return;
    float acc = be1[k];
#pragma unroll
    for (int i = 0; i < EIN; i++) acc += ef[e * EIN + i] * We1[i * EH + k];
    float v = fmaxf(acc, 0.0f);
    __nv_bfloat16 hi = __float2bfloat16(v);
    __nv_bfloat16 lo = __float2bfloat16(v - __bfloat162float(hi));
    __nv_bfloat16* row = g_h1c + (size_t)e * KC;
    row[k] = hi;
    row[128 + k] = hi;
    row[256 + k] = lo;
}

// ---------------- We2 transpose -> concatenated split [hi|lo|hi] ----------------
__global__ void we2_prep(const float* __restrict__ We2) {
    int idx = blockIdx.x * blockDim.x + threadIdx.x;  // 4096*128
    if (idx >= 4096 * EH) return;
    int n = idx >> 7;
    int k = idx & 127;
    float v = We2[k * 4096 + n];
    __nv_bfloat16 hi = __float2bfloat16(v);
    __nv_bfloat16 lo = __float2bfloat16(v - __bfloat162float(hi));
    __nv_bfloat16* row = g_We2c + (size_t)n * KC;
    row[k] = hi;
    row[128 + k] = lo;
    row[256 + k] = hi;
}

// ---------------- pipelined bf16 GEMM: w_edge = h1c @ We2c^T + be2 ----------------
// CTA 128(M) x 128(N), K=384, BK=64, 2-stage cp.async, XOR-swizzled smem.
#define BKT 64
#define STAGE_BYTES 16384              // 128 rows * 128B
#define B_BASE 32768
#define WSMEM_TOTAL 65536

__global__ void __launch_bounds__(256, 2) wedge_gemm_mma(const float* __restrict__ be2) {
    extern __shared__ char smem[];
    const uint32_t sbase = smem_u32(smem);
    const int tid = threadIdx.x;
    const int wid = tid >> 5;
    const int lane = tid & 31;
    const int block_n = blockIdx.x * 128;
    const int block_m = blockIdx.y * 128;

    const int wm = wid & 3;
    const int wn = wid >> 2;
    const int m_off = wm * 32;
    const int n_off = wn * 64;

    float acc[2][8][4];
#pragma unroll
    for (int mt = 0; mt < 2; mt++)
#pragma unroll
        for (int nt = 0; nt < 8; nt++)
#pragma unroll
            for (int q = 0; q < 4; q++) acc[mt][nt][q] = 0.0f;

    // per-thread load mapping: 4 A chunks + 4 B chunks per stage
    // chunkid = tid + i*256: row = chunkid>>3 (0..127), c = chunkid&7 (16B unit)
    auto load_stage = [&](int stage, int kt) {
        const int k0 = kt * BKT;  // bf16 units
        const uint32_t As = sbase + stage * STAGE_BYTES;
        const uint32_t Bs = sbase + B_BASE + stage * STAGE_BYTES;
#pragma unroll
        for (int i = 0; i < 4; i++) {
            int cid = tid + i * 256;
            int r = cid >> 3;
            int c = cid & 7;
            int e = block_m + r;
            const void* gsrc = g_h1c + (size_t)e * KC + k0 + c * 8;
            uint32_t sdst = As + r * 128 + ((c ^ (r & 7)) << 4);
            cp_async16(sdst, gsrc, (e < N_EDGES) ? 16 : 0);
        }
#pragma unroll
        for (int i = 0; i < 4; i++) {
            int cid = tid + i * 256;
            int r = cid >> 3;
            int c = cid & 7;
            int n = block_n + r;
            const void* gsrc = g_We2c + (size_t)n * KC + k0 + c * 8;
            uint32_t sdst = Bs + r * 128 + ((c ^ (r & 7)) << 4);
            cp_async16(sdst, gsrc, 16);
        }
    };

    const int a_row_l = lane & 15;
    const int a_uoff = lane >> 4;              // 16B-unit offset 0/1
    const int b_row_l = ((lane >> 4) << 3) + (lane & 7);
    const int b_uoff = (lane >> 3) & 1;

    load_stage(0, 0);
    CP_COMMIT();

    const int NKT = KC / BKT;  // 6
#pragma unroll 1
    for (int kt = 0; kt < NKT; kt++) {
        if (kt + 1 < NKT) {
            load_stage((kt + 1) & 1, kt + 1);
            CP_COMMIT();
            CP_WAIT(1);
        } else {
            CP_WAIT(0);
        }
        __syncthreads();
        const uint32_t As = sbase + (kt & 1) * STAGE_BYTES;
        const uint32_t Bs = sbase + B_BASE + (kt & 1) * STAGE_BYTES;
#pragma unroll
        for (int ks = 0; ks < 4; ks++) {
            const int ub = ks * 2;  // 16B-unit base for this k16
            uint32_t a[2][4];
#pragma unroll
            for (int mt = 0; mt < 2; mt++) {
                int r = m_off + mt * 16 + a_row_l;
                int u = ub + a_uoff;
                ldsm_x4(a[mt][0], a[mt][1], a[mt][2], a[mt][3],
                        As + r * 128 + ((u ^ (r & 7)) << 4));
            }
            uint32_t b[8][2];
#pragma unroll
            for (int np = 0; np < 4; np++) {
                int r = n_off + np * 16 + b_row_l;
                int u = ub + b_uoff;
                uint32_t r0, r1, r2, r3;
                ldsm_x4(r0, r1, r2, r3, Bs + r * 128 + ((u ^ (r & 7)) << 4));
                b[np * 2][0] = r0; b[np * 2][1] = r1;
                b[np * 2 + 1][0] = r2; b[np * 2 + 1][1] = r3;
            }
#pragma unroll
            for (int mt = 0; mt < 2; mt++)
#pragma unroll
                for (int nt = 0; nt < 8; nt++)
                    mma_bf16(acc[mt][nt][0], acc[mt][nt][1], acc[mt][nt][2], acc[mt][nt][3],
                             a[mt][0], a[mt][1], a[mt][2], a[mt][3],
                             b[nt][0], b[nt][1]);
        }
        __syncthreads();
    }

    // epilogue: add bias, store fp32
    const int qrow = lane >> 2;
    const int qcol = (lane & 3) * 2;
#pragma unroll
    for (int mt = 0; mt < 2; mt++) {
        int r0 = block_m + m_off + mt * 16 + qrow;
        int r1 = r0 + 8;
#pragma unroll
        for (int nt = 0; nt < 8; nt++) {
            int col = block_n + n_off + nt * 8 + qcol;
            float bx = be2[col];
            float by = be2[col + 1];
            if (r0 < N_EDGES) {
                float2 v0 = make_float2(acc[mt][nt][0] + bx, acc[mt][nt][1] + by);
                *(float2*)(g_wedge + (size_t)r0 * 4096 + col) = v0;
            }
            if (r1 < N_EDGES) {
                float2 v1 = make_float2(acc[mt][nt][2] + bx, acc[mt][nt][3] + by);
                *(float2*)(g_wedge + (size_t)r1 * 4096 + col) = v1;
            }
        }
    }
}

// ---------------- init agg with conv_bias ----------------
__global__ void init_agg(const float* __restrict__ conv_bias) {
    int i = blockIdx.x * blockDim.x + threadIdx.x;
    if (i < N_NODES * H) g_agg[i] = conv_bias[i & 63];
}

// ---------------- message + scatter: warp per edge ----------------
__global__ void msg_kernel(const int* __restrict__ src, const int* __restrict__ dst) {
    int widx = (blockIdx.x * blockDim.x + threadIdx.x) >> 5;
    int lane = threadIdx.x & 31;
    if (widx >= N_EDGES) return;
    int s = src[widx];
    int d = dst[widx];
    float x0 = g_x[s * H + lane];
    float x1 = g_x[s * H + 32 + lane];
    const float2* w2 = (const float2*)(g_wedge + (size_t)widx * H * H);
    float m0 = 0.f, m1 = 0.f;
#pragma unroll 8
    for (int i = 0; i < 32; i++) {
        float xi = __shfl_sync(0xffffffffu, x0, i);
        float2 wv = w2[i * 32 + lane];
        m0 += xi * wv.x;
        m1 += xi * wv.y;
    }
#pragma unroll 8
    for (int i = 0; i < 32; i++) {
        float xi = __shfl_sync(0xffffffffu, x1, i);
        float2 wv = w2[(i + 32) * 32 + lane];
        m0 += xi * wv.x;
        m1 += xi * wv.y;
    }
    atomicAdd(&g_agg[d * H + 2 * lane], m0);
    atomicAdd(&g_agg[d * H + 2 * lane + 1], m1);
}

// ---------------- relu step ----------------
__global__ void relu_step() {
    int i = blockIdx.x * blockDim.x + threadIdx.x;
    if (i < N_NODES * H) g_x[i] = fmaxf(g_agg[i], 0.0f);
}

// ---------------- BatchNorm ----------------
__global__ void bn_zero() {
    int t = threadIdx.x;
    if (t < H) {
        g_sum[t] = 0.f;
        g_sumsq[t] = 0.f;
    }
}

__global__ void bn_reduce() {
    int t = threadIdx.x;
    int h = t & 63;
    int rsub = t >> 6;
    float s = 0.f, q = 0.f;
    for (int r = blockIdx.x * 4 + rsub; r < N_NODES; r += gridDim.x * 4) {
        float v = g_x[r * H + h];
        s += v;
        q += v * v;
    }
    __shared__ float ss[256], sq[256];
    ss[t] = s;
    sq[t] = q;
    __syncthreads();
    if (t < 64) {
        s = ss[t] + ss[t + 64] + ss[t + 128] + ss[t + 192];
        q = sq[t] + sq[t + 64] + sq[t + 128] + sq[t + 192];
        atomicAdd(&g_sum[h], s);
        atomicAdd(&g_sumsq[h], q);
    }
}

__global__ void bn_apply(const float* __restrict__ gamma, const float* __restrict__ beta,
                         float* __restrict__ out) {
    int i = blockIdx.x * blockDim.x + threadIdx.x;
    if (i >= N_NODES * H) return;
    int h = i & 63;
    float mean = g_sum[h] / (float)N_NODES;
    float var = g_sumsq[h] / (float)N_NODES - mean * mean;
    out[i] = (g_x[i] - mean) * rsqrtf(var + 1e-5f) * gamma[h] + beta[h];
}

// ---------------- launch ----------------
extern "C" void kernel_launch(void* const* d_in, const int* in_sizes, int n_in,
                              void* d_out, int out_size) {
    const float* n_feat    = (const float*)d_in[0];
    const float* e_feat    = (const float*)d_in[1];
    const int*   src       = (const int*)d_in[2];
    const int*   dst       = (const int*)d_in[3];
    const float* W0        = (const float*)d_in[4];
    const float* b0        = (const float*)d_in[5];
    const float* We1       = (const float*)d_in[6];
    const float* be1       = (const float*)d_in[7];
    const float* We2       = (const float*)d_in[8];
    const float* be2       = (const float*)d_in[9];
    const float* conv_bias = (const float*)d_in[10];
    const float* gamma     = (const float*)d_in[11];
    const float* beta      = (const float*)d_in[12];
    float* out = (float*)d_out;

    cudaFuncSetAttribute(wedge_gemm_mma, cudaFuncAttributeMaxDynamicSharedMemorySize,
                         WSMEM_TOTAL);

    node_mlp<<<N_NODES, 64>>>(n_feat, W0, b0);
    edge_h1<<<(N_EDGES * EH) / 256, 256>>>(e_feat, We1, be1);
    we2_prep<<<(4096 * EH) / 256, 256>>>(We2);

    // x = N-blocks fast so each M-block's A tile stays hot in L2
    dim3 ggrid(4096 / 128, (N_EDGES + 127) / 128);
    wedge_gemm_mma<<<ggrid, 256, WSMEM_TOTAL>>>(be2);

    int nh = N_NODES * H;
    int eb = (N_EDGES * 32 + 255) / 256;
    for (int step = 0; step < STEPS; step++) {
        init_agg<<<(nh + 255) / 256, 256>>>(conv_bias);
        msg_kernel<<<eb, 256>>>(src, dst);
        relu_step<<<(nh + 255) / 256, 256>>>();
    }

    bn_zero<<<1, 64>>>();
    bn_reduce<<<100, 256>>>();
    bn_apply<<<(nh + 255) / 256, 256>>>(gamma, beta, out);
    (void)in_sizes; (void)n_in; (void)out_size;
}

// round 6
// speedup vs baseline: 1.8989x; 1.0174x over previous
#include <cuda_runtime.h>
#include <cuda_bf16.h>
#include <cstdint>

#define N_NODES 10000
#define N_EDGES 100000
#define DIN 64
#define H 64
#define EIN 16
#define EH 128
#define STEPS 3
#define KC 384   // concatenated split K

// ---------------- device scratch ----------------
__device__ float g_x[N_NODES * H];
__device__ float g_agg[N_NODES * H];
__device__ __nv_bfloat16 g_h1c[(size_t)N_EDGES * KC];   // [hi | hi | lo]
__device__ __nv_bfloat16 g_We2c[4096 * KC];             // [hi | lo | hi] (row = out col n)
__device__ float g_wedge[(size_t)N_EDGES * H * H];      // 1.64 GB fp32
__device__ float g_sum[H];
__device__ float g_sumsq[H];

// ---------------- helpers ----------------
__device__ __forceinline__ uint32_t smem_u32(const void* p) {
    uint32_t a;
    asm("{ .reg .u64 t; cvta.to.shared.u64 t, %1; cvt.u32.u64 %0, t; }" : "=r"(a) : "l"(p));
    return a;
}
__device__ __forceinline__ void cp_async16(uint32_t dst, const void* src, int src_bytes) {
    asm volatile("cp.async.cg.shared.global [%0], [%1], 16, %2;"
                 :: "r"(dst), "l"(src), "r"(src_bytes));
}
#define CP_COMMIT() asm volatile("cp.async.commit_group;" ::: "memory")
#define CP_WAIT(n)  asm volatile("cp.async.wait_group %0;" :: "n"(n) : "memory")

__device__ __forceinline__ void ldsm_x4(uint32_t& r0, uint32_t& r1, uint32_t& r2,
                                        uint32_t& r3, uint32_t addr) {
    asm volatile("ldmatrix.sync.aligned.m8n8.x4.shared.b16 {%0,%1,%2,%3}, [%4];"
                 : "=r"(r0), "=r"(r1), "=r"(r2), "=r"(r3) : "r"(addr));
}
__device__ __forceinline__ void mma_bf16(float& c0, float& c1, float& c2, float& c3,
                                         uint32_t a0, uint32_t a1, uint32_t a2, uint32_t a3,
                                         uint32_t b0, uint32_t b1) {
    asm volatile(
        "mma.sync.aligned.m16n8k16.row.col.f32.bf16.bf16.f32 "
        "{%0,%1,%2,%3}, {%4,%5,%6,%7}, {%8,%9}, {%0,%1,%2,%3};"
        : "+f"(c0), "+f"(c1), "+f"(c2), "+f"(c3)
        : "r"(a0), "r"(a1), "r"(a2), "r"(a3), "r"(b0), "r"(b1));
}

// ---------------- node MLP ----------------
__global__ void node_mlp(const float* __restrict__ nf, const float* __restrict__ W0,
                         const float* __restrict__ b0) {
    int n = blockIdx.x;
    int h = threadIdx.x;
    __shared__ float xs[DIN];
    xs[h] = nf[n * DIN + h];
    __syncthreads();
    float acc = b0[h];
#pragma unroll
    for (int i = 0; i < DIN; i++) acc += xs[i] * W0[i * H + h];
    g_x[n * H + h] = fmaxf(acc, 0.0f);
}

// ---------------- edge hidden -> concatenated split [hi|hi|lo] ----------------
__global__ void edge_h1(const float* __restrict__ ef, const float* __restrict__ We1,
                        const float* __restrict__ be1) {
    int gid = blockIdx.x * blockDim.x + threadIdx.x;
    int e = gid >> 7;
    int k = gid & 127;
    if (e >= N_EDGES) return;
    float acc = be1[k];
#pragma unroll
    for (int i = 0; i < EIN; i++) acc += ef[e * EIN + i] * We1[i * EH + k];
    float v = fmaxf(acc, 0.0f);
    __nv_bfloat16 hi = __float2bfloat16(v);
    __nv_bfloat16 lo = __float2bfloat16(v - __bfloat162float(hi));
    __nv_bfloat16* row = g_h1c + (size_t)e * KC;
    row[k] = hi;
    row[128 + k] = hi;
    row[256 + k] = lo;
}

// ---------------- We2 transpose -> concatenated split [hi|lo|hi] ----------------
__global__ void we2_prep(const float* __restrict__ We2) {
    int idx = blockIdx.x * blockDim.x + threadIdx.x;  // 4096*128
    if (idx >= 4096 * EH) return;
    int n = idx >> 7;
    int k = idx & 127;
    float v = We2[k * 4096 + n];
    __nv_bfloat16 hi = __float2bfloat16(v);
    __nv_bfloat16 lo = __float2bfloat16(v - __bfloat162float(hi));
    __nv_bfloat16* row = g_We2c + (size_t)n * KC;
    row[k] = hi;
    row[128 + k] = lo;
    row[256 + k] = hi;
}

// ---------------- pipelined bf16 GEMM: w_edge = h1c @ We2c^T + be2 ----------------
// CTA 128(M) x 128(N), 128 threads, warp tile 64x64 (2x2 warps).
// K=384, BK=64, 3-stage cp.async ring, XOR-swizzled smem.
#define BKT 64
#define STAGE_BYTES 32768              // A 16KB + B 16KB
#define WSMEM_TOTAL (3 * STAGE_BYTES)  // 96 KB

__global__ void __launch_bounds__(128, 2) wedge_gemm_mma(const float* __restrict__ be2) {
    extern __shared__ char smem[];
    const uint32_t sbase = smem_u32(smem);
    const int tid = threadIdx.x;
    const int wid = tid >> 5;
    const int lane = tid & 31;
    const int block_n = blockIdx.x * 128;
    const int block_m = blockIdx.y * 128;

    const int wm = wid & 1;        // M half
    const int wn = wid >> 1;       // N half
    const int m_off = wm * 64;
    const int n_off = wn * 64;

    float acc[4][8][4];
#pragma unroll
    for (int mt = 0; mt < 4; mt++)
#pragma unroll
        for (int nt = 0; nt < 8; nt++)
#pragma unroll
            for (int q = 0; q < 4; q++) acc[mt][nt][q] = 0.0f;

    // per-thread load mapping: 8 A chunks + 8 B chunks per stage (16B each)
    auto load_stage = [&](int stage, int kt) {
        const int k0 = kt * BKT;
        const uint32_t As = sbase + stage * STAGE_BYTES;
        const uint32_t Bs = As + 16384;
#pragma unroll
        for (int i = 0; i < 8; i++) {
            int cid = tid + i * 128;
            int r = cid >> 3;
            int c = cid & 7;
            int e = block_m + r;
            const void* gsrc = g_h1c + (size_t)e * KC + k0 + c * 8;
            uint32_t sdst = As + r * 128 + ((c ^ (r & 7)) << 4);
            cp_async16(sdst, gsrc, (e < N_EDGES) ? 16 : 0);
        }
#pragma unroll
        for (int i = 0; i < 8; i++) {
            int cid = tid + i * 128;
            int r = cid >> 3;
            int c = cid & 7;
            int n = block_n + r;
            const void* gsrc = g_We2c + (size_t)n * KC + k0 + c * 8;
            uint32_t sdst = Bs + r * 128 + ((c ^ (r & 7)) << 4);
            cp_async16(sdst, gsrc, 16);
        }
    };

    const int a_row_l = lane & 15;
    const int a_uoff = lane >> 4;
    const int b_row_l = ((lane >> 4) << 3) + (lane & 7);
    const int b_uoff = (lane >> 3) & 1;

    load_stage(0, 0);
    CP_COMMIT();
    load_stage(1, 1);
    CP_COMMIT();

    const int NKT = KC / BKT;  // 6
#pragma unroll 1
    for (int kt = 0; kt < NKT; kt++) {
        CP_WAIT(1);            // stage kt resident
        __syncthreads();       // all warps done with buffer (kt-1)%3 == (kt+2)%3
        if (kt + 2 < NKT) {
            load_stage((kt + 2) % 3, kt + 2);
            CP_COMMIT();
        }
        const uint32_t As = sbase + (kt % 3) * STAGE_BYTES;
        const uint32_t Bs = As + 16384;
#pragma unroll
        for (int ks = 0; ks < 4; ks++) {
            const int ub = ks * 2;
            uint32_t a[4][4];
#pragma unroll
            for (int mt = 0; mt < 4; mt++) {
                int r = m_off + mt * 16 + a_row_l;
                int u = ub + a_uoff;
                ldsm_x4(a[mt][0], a[mt][1], a[mt][2], a[mt][3],
                        As + r * 128 + ((u ^ (r & 7)) << 4));
            }
            uint32_t b[8][2];
#pragma unroll
            for (int np = 0; np < 4; np++) {
                int r = n_off + np * 16 + b_row_l;
                int u = ub + b_uoff;
                uint32_t r0, r1, r2, r3;
                ldsm_x4(r0, r1, r2, r3, Bs + r * 128 + ((u ^ (r & 7)) << 4));
                b[np * 2][0] = r0; b[np * 2][1] = r1;
                b[np * 2 + 1][0] = r2; b[np * 2 + 1][1] = r3;
            }
#pragma unroll
            for (int mt = 0; mt < 4; mt++)
#pragma unroll
                for (int nt = 0; nt < 8; nt++)
                    mma_bf16(acc[mt][nt][0], acc[mt][nt][1], acc[mt][nt][2], acc[mt][nt][3],
                             a[mt][0], a[mt][1], a[mt][2], a[mt][3],
                             b[nt][0], b[nt][1]);
        }
        __syncthreads();
    }

    // epilogue: add bias, store fp32
    const int qrow = lane >> 2;
    const int qcol = (lane & 3) * 2;
#pragma unroll
    for (int mt = 0; mt < 4; mt++) {
        int r0 = block_m + m_off + mt * 16 + qrow;
        int r1 = r0 + 8;
#pragma unroll
        for (int nt = 0; nt < 8; nt++) {
            int col = block_n + n_off + nt * 8 + qcol;
            float bx = be2[col];
            float by = be2[col + 1];
            if (r0 < N_EDGES) {
                float2 v0 = make_float2(acc[mt][nt][0] + bx, acc[mt][nt][1] + by);
                *(float2*)(g_wedge + (size_t)r0 * 4096 + col) = v0;
            }
            if (r1 < N_EDGES) {
                float2 v1 = make_float2(acc[mt][nt][2] + bx, acc[mt][nt][3] + by);
                *(float2*)(g_wedge + (size_t)r1 * 4096 + col) = v1;
            }
        }
    }
}

// ---------------- init agg with conv_bias ----------------
__global__ void init_agg(const float* __restrict__ conv_bias) {
    int i = blockIdx.x * blockDim.x + threadIdx.x;
    if (i < N_NODES * H) g_agg[i] = conv_bias[i & 63];
}

// ---------------- message + scatter: warp per edge ----------------
__global__ void msg_kernel(const int* __restrict__ src, const int* __restrict__ dst) {
    int widx = (blockIdx.x * blockDim.x + threadIdx.x) >> 5;
    int lane = threadIdx.x & 31;
    if (widx >= N_EDGES) return;
    int s = src[widx];
    int d = dst[widx];
    float x0 = g_x[s * H + lane];
    float x1 = g_x[s * H + 32 + lane];
    const float2* w2 = (const float2*)(g_wedge + (size_t)widx * H * H);
    float m0 = 0.f, m1 = 0.f;
#pragma unroll 8
    for (int i = 0; i < 32; i++) {
        float xi = __shfl_sync(0xffffffffu, x0, i);
        float2 wv = w2[i * 32 + lane];
        m0 += xi * wv.x;
        m1 += xi * wv.y;
    }
#pragma unroll 8
    for (int i = 0; i < 32; i++) {
        float xi = __shfl_sync(0xffffffffu, x1, i);
        float2 wv = w2[(i + 32) * 32 + lane];
        m0 += xi * wv.x;
        m1 += xi * wv.y;
    }
    atomicAdd(&g_agg[d * H + 2 * lane], m0);
    atomicAdd(&g_agg[d * H + 2 * lane + 1], m1);
}

// ---------------- relu step ----------------
__global__ void relu_step() {
    int i = blockIdx.x * blockDim.x + threadIdx.x;
    if (i < N_NODES * H) g_x[i] = fmaxf(g_agg[i], 0.0f);
}

// ---------------- BatchNorm ----------------
__global__ void bn_zero() {
    int t = threadIdx.x;
    if (t < H) {
        g_sum[t] = 0.f;
        g_sumsq[t] = 0.f;
    }
}

__global__ void bn_reduce() {
    int t = threadIdx.x;
    int h = t & 63;
    int rsub = t >> 6;
    float s = 0.f, q = 0.f;
    for (int r = blockIdx.x * 4 + rsub; r < N_NODES; r += gridDim.x * 4) {
        float v = g_x[r * H + h];
        s += v;
        q += v * v;
    }
    __shared__ float ss[256], sq[256];
    ss[t] = s;
    sq[t] = q;
    __syncthreads();
    if (t < 64) {
        s = ss[t] + ss[t + 64] + ss[t + 128] + ss[t + 192];
        q = sq[t] + sq[t + 64] + sq[t + 128] + sq[t + 192];
        atomicAdd(&g_sum[h], s);
        atomicAdd(&g_sumsq[h], q);
    }
}

__global__ void bn_apply(const float* __restrict__ gamma, const float* __restrict__ beta,
                         float* __restrict__ out) {
    int i = blockIdx.x * blockDim.x + threadIdx.x;
    if (i >= N_NODES * H) return;
    int h = i & 63;
    float mean = g_sum[h] / (float)N_NODES;
    float var = g_sumsq[h] / (float)N_NODES - mean * mean;
    out[i] = (g_x[i] - mean) * rsqrtf(var + 1e-5f) * gamma[h] + beta[h];
}

// ---------------- launch ----------------
extern "C" void kernel_launch(void* const* d_in, const int* in_sizes, int n_in,
                              void* d_out, int out_size) {
    const float* n_feat    = (const float*)d_in[0];
    const float* e_feat    = (const float*)d_in[1];
    const int*   src       = (const int*)d_in[2];
    const int*   dst       = (const int*)d_in[3];
    const float* W0        = (const float*)d_in[4];
    const float* b0        = (const float*)d_in[5];
    const float* We1       = (const float*)d_in[6];
    const float* be1       = (const float*)d_in[7];
    const float* We2       = (const float*)d_in[8];
    const float* be2       = (const float*)d_in[9];
    const float* conv_bias = (const float*)d_in[10];
    const float* gamma     = (const float*)d_in[11];
    const float* beta      = (const float*)d_in[12];
    float* out = (float*)d_out;

    cudaFuncSetAttribute(wedge_gemm_mma, cudaFuncAttributeMaxDynamicSharedMemorySize,
                         WSMEM_TOTAL);

    node_mlp<<<N_NODES, 64>>>(n_feat, W0, b0);
    edge_h1<<<(N_EDGES * EH) / 256, 256>>>(e_feat, We1, be1);
    we2_prep<<<(4096 * EH) / 256, 256>>>(We2);

    // x = N-blocks fast so each M-block's A tile stays hot in L2
    dim3 ggrid(4096 / 128, (N_EDGES + 127) / 128);
    wedge_gemm_mma<<<ggrid, 128, WSMEM_TOTAL>>>(be2);

    int nh = N_NODES * H;
    int eb = (N_EDGES * 32 + 255) / 256;
    for (int step = 0; step < STEPS; step++) {
        init_agg<<<(nh + 255) / 256, 256>>>(conv_bias);
        msg_kernel<<<eb, 256>>>(src, dst);
        relu_step<<<(nh + 255) / 256, 256>>>();
    }

    bn_zero<<<1, 64>>>();
    bn_reduce<<<100, 256>>>();
    bn_apply<<<(nh + 255) / 256, 256>>>(gamma, beta, out);
    (void)in_sizes; (void)n_in; (void)out_size;
}

// round 7
// speedup vs baseline: 3.4188x; 1.8004x over previous
#include <cuda_runtime.h>
#include <cuda_bf16.h>
#include <cstdint>

#define N_NODES 10000
#define N_EDGES 100000
#define DIN 64
#define H 64
#define EIN 16
#define EH 128
#define STEPS 3
#define KC2 192          // split-concat K for T-GEMM (64*3)
#define TCOLS 8192       // 128*64

// ---------------- device scratch ----------------
__device__ float g_x[N_NODES * H];
__device__ __nv_bfloat16 g_xc[N_NODES * KC2];     // x split [hi|hi|lo]
__device__ float g_agg[N_NODES * H];
__device__ float g_h1f[(size_t)N_EDGES * EH];     // edge hidden, fp32
__device__ __nv_bfloat16 g_WtC[TCOLS * KC2];      // W'[col][j] split [hi|lo|hi]
__device__ float g_T[(size_t)N_NODES * TCOLS];    // 327 MB
__device__ float g_B[N_NODES * H];
__device__ int g_cnt[N_NODES];
__device__ int g_fill[N_NODES];
__device__ int g_rowptr[N_NODES + 1];
__device__ int g_eidx[N_EDGES];
__device__ float g_sum[H];
__device__ float g_sumsq[H];

// ---------------- helpers ----------------
__device__ __forceinline__ uint32_t smem_u32(const void* p) {
    uint32_t a;
    asm("{ .reg .u64 t; cvta.to.shared.u64 t, %1; cvt.u32.u64 %0, t; }" : "=r"(a) : "l"(p));
    return a;
}
__device__ __forceinline__ void cp_async16(uint32_t dst, const void* src, int src_bytes) {
    asm volatile("cp.async.cg.shared.global [%0], [%1], 16, %2;"
                 :: "r"(dst), "l"(src), "r"(src_bytes));
}
#define CP_COMMIT() asm volatile("cp.async.commit_group;" ::: "memory")
#define CP_WAIT(n)  asm volatile("cp.async.wait_group %0;" :: "n"(n) : "memory")

__device__ __forceinline__ void ldsm_x4(uint32_t& r0, uint32_t& r1, uint32_t& r2,
                                        uint32_t& r3, uint32_t addr) {
    asm volatile("ldmatrix.sync.aligned.m8n8.x4.shared.b16 {%0,%1,%2,%3}, [%4];"
                 : "=r"(r0), "=r"(r1), "=r"(r2), "=r"(r3) : "r"(addr));
}
__device__ __forceinline__ void mma_bf16(float& c0, float& c1, float& c2, float& c3,
                                         uint32_t a0, uint32_t a1, uint32_t a2, uint32_t a3,
                                         uint32_t b0, uint32_t b1) {
    asm volatile(
        "mma.sync.aligned.m16n8k16.row.col.f32.bf16.bf16.f32 "
        "{%0,%1,%2,%3}, {%4,%5,%6,%7}, {%8,%9}, {%0,%1,%2,%3};"
        : "+f"(c0), "+f"(c1), "+f"(c2), "+f"(c3)
        : "r"(a0), "r"(a1), "r"(a2), "r"(a3), "r"(b0), "r"(b1));
}
__device__ __forceinline__ void split_store(float v, __nv_bfloat16* row, int j) {
    __nv_bfloat16 hi = __float2bfloat16(v);
    __nv_bfloat16 lo = __float2bfloat16(v - __bfloat162float(hi));
    row[j] = hi;
    row[64 + j] = hi;
    row[128 + j] = lo;
}

// ---------------- node MLP (writes x and x-split) ----------------
__global__ void node_mlp(const float* __restrict__ nf, const float* __restrict__ W0,
                         const float* __restrict__ b0) {
    int n = blockIdx.x;
    int h = threadIdx.x;
    __shared__ float xs[DIN];
    xs[h] = nf[n * DIN + h];
    __syncthreads();
    float acc = b0[h];
#pragma unroll
    for (int i = 0; i < DIN; i++) acc += xs[i] * W0[i * H + h];
    float v = fmaxf(acc, 0.0f);
    g_x[n * H + h] = v;
    split_store(v, g_xc + n * KC2, h);
}

// ---------------- edge hidden (fp32) ----------------
__global__ void edge_h1(const float* __restrict__ ef, const float* __restrict__ We1,
                        const float* __restrict__ be1) {
    int gid = blockIdx.x * blockDim.x + threadIdx.x;
    int e = gid >> 7;
    int k = gid & 127;
    if (e >= N_EDGES) return;
    float acc = be1[k];
#pragma unroll
    for (int i = 0; i < EIN; i++) acc += ef[e * EIN + i] * We1[i * EH + k];
    g_h1f[gid] = fmaxf(acc, 0.0f);
}

// ---------------- W' prep: W'[col=k*64+o][j] = We2[k][j*64+o], split [hi|lo|hi] ----------------
__global__ void wt_prep(const float* __restrict__ We2) {
    int idx = blockIdx.x * blockDim.x + threadIdx.x;  // TCOLS*64
    if (idx >= TCOLS * 64) return;
    int col = idx >> 6;
    int j = idx & 63;
    int k = col >> 6;
    int o = col & 63;
    float v = We2[k * 4096 + j * 64 + o];
    __nv_bfloat16 hi = __float2bfloat16(v);
    __nv_bfloat16 lo = __float2bfloat16(v - __bfloat162float(hi));
    __nv_bfloat16* row = g_WtC + col * KC2;
    row[j] = hi;
    row[64 + j] = lo;
    row[128 + j] = hi;
}

// ---------------- edge sort by src: hist / scan / scatter ----------------
__global__ void zero_bins() {
    int i = blockIdx.x * blockDim.x + threadIdx.x;
    if (i < N_NODES) { g_cnt[i] = 0; g_fill[i] = 0; }
}
__global__ void hist_kernel(const int* __restrict__ src) {
    int e = blockIdx.x * blockDim.x + threadIdx.x;
    if (e < N_EDGES) atomicAdd(&g_cnt[src[e]], 1);
}
__global__ void scan_kernel() {
    __shared__ int ts[1024];
    int t = threadIdx.x;
    int base = t * 10;
    int c[10];
    int tot = 0;
#pragma unroll
    for (int i = 0; i < 10; i++) {
        int idx = base + i;
        c[i] = (idx < N_NODES) ? g_cnt[idx] : 0;
        tot += c[i];
    }
    ts[t] = tot;
    __syncthreads();
    for (int off = 1; off < 1024; off <<= 1) {
        int v = (t >= off) ? ts[t - off] : 0;
        __syncthreads();
        ts[t] += v;
        __syncthreads();
    }
    int run = ts[t] - tot;  // exclusive prefix
#pragma unroll
    for (int i = 0; i < 10; i++) {
        int idx = base + i;
        if (idx < N_NODES) { g_rowptr[idx] = run; run += c[i]; }
    }
    if (t == 1023) g_rowptr[N_NODES] = N_EDGES;
}
__global__ void scatter_kernel(const int* __restrict__ src) {
    int e = blockIdx.x * blockDim.x + threadIdx.x;
    if (e >= N_EDGES) return;
    int s = src[e];
    int pos = g_rowptr[s] + atomicAdd(&g_fill[s], 1);
    g_eidx[pos] = e;
}

// ---------------- per-step: B[n,o] = sum_j x[n,j]*be2[j*64+o] ----------------
__global__ void b_term(const float* __restrict__ be2) {
    int n = blockIdx.x;
    int o = threadIdx.x;
    __shared__ float xs[64];
    xs[o] = g_x[n * 64 + o];
    __syncthreads();
    float acc = 0.f;
#pragma unroll
    for (int j = 0; j < 64; j++) acc += xs[j] * be2[j * 64 + o];
    g_B[n * 64 + o] = acc;
}

// ---------------- T-GEMM: T[n, col] = xc[n] . WtC[col], M=10000 N=8192 K=192 ----------------
#define BKT 64
#define STAGE_BYTES 32768
#define TG_SMEM (3 * STAGE_BYTES)
#define NKT2 3

__global__ void __launch_bounds__(128, 2) tgemm() {
    extern __shared__ char smem[];
    const uint32_t sbase = smem_u32(smem);
    const int tid = threadIdx.x;
    const int wid = tid >> 5;
    const int lane = tid & 31;
    const int block_n = blockIdx.x * 128;
    const int block_m = blockIdx.y * 128;

    const int wm = wid & 1;
    const int wn = wid >> 1;
    const int m_off = wm * 64;
    const int n_off = wn * 64;

    float acc[4][8][4];
#pragma unroll
    for (int mt = 0; mt < 4; mt++)
#pragma unroll
        for (int nt = 0; nt < 8; nt++)
#pragma unroll
            for (int q = 0; q < 4; q++) acc[mt][nt][q] = 0.0f;

    auto load_stage = [&](int stage, int kt) {
        const int k0 = kt * BKT;
        const uint32_t As = sbase + stage * STAGE_BYTES;
        const uint32_t Bs = As + 16384;
#pragma unroll
        for (int i = 0; i < 8; i++) {
            int cid = tid + i * 128;
            int r = cid >> 3;
            int c = cid & 7;
            int n = block_m + r;
            const void* gsrc = g_xc + (size_t)n * KC2 + k0 + c * 8;
            uint32_t sdst = As + r * 128 + ((c ^ (r & 7)) << 4);
            cp_async16(sdst, gsrc, (n < N_NODES) ? 16 : 0);
        }
#pragma unroll
        for (int i = 0; i < 8; i++) {
            int cid = tid + i * 128;
            int r = cid >> 3;
            int c = cid & 7;
            int col = block_n + r;
            const void* gsrc = g_WtC + (size_t)col * KC2 + k0 + c * 8;
            uint32_t sdst = Bs + r * 128 + ((c ^ (r & 7)) << 4);
            cp_async16(sdst, gsrc, 16);
        }
    };

    const int a_row_l = lane & 15;
    const int a_uoff = lane >> 4;
    const int b_row_l = ((lane >> 4) << 3) + (lane & 7);
    const int b_uoff = (lane >> 3) & 1;

    load_stage(0, 0);
    CP_COMMIT();
    load_stage(1, 1);
    CP_COMMIT();

#pragma unroll
    for (int kt = 0; kt < NKT2; kt++) {
        if (kt == NKT2 - 1) { CP_WAIT(0); } else { CP_WAIT(1); }
        __syncthreads();
        if (kt + 2 < NKT2) {
            load_stage(kt + 2, kt + 2);
            CP_COMMIT();
        }
        const uint32_t As = sbase + kt * STAGE_BYTES;
        const uint32_t Bs = As + 16384;
#pragma unroll
        for (int ks = 0; ks < 4; ks++) {
            const int ub = ks * 2;
            uint32_t a[4][4];
#pragma unroll
            for (int mt = 0; mt < 4; mt++) {
                int r = m_off + mt * 16 + a_row_l;
                int u = ub + a_uoff;
                ldsm_x4(a[mt][0], a[mt][1], a[mt][2], a[mt][3],
                        As + r * 128 + ((u ^ (r & 7)) << 4));
            }
            uint32_t b[8][2];
#pragma unroll
            for (int np = 0; np < 4; np++) {
                int r = n_off + np * 16 + b_row_l;
                int u = ub + b_uoff;
                uint32_t r0, r1, r2, r3;
                ldsm_x4(r0, r1, r2, r3, Bs + r * 128 + ((u ^ (r & 7)) << 4));
                b[np * 2][0] = r0; b[np * 2][1] = r1;
                b[np * 2 + 1][0] = r2; b[np * 2 + 1][1] = r3;
            }
#pragma unroll
            for (int mt = 0; mt < 4; mt++)
#pragma unroll
                for (int nt = 0; nt < 8; nt++)
                    mma_bf16(acc[mt][nt][0], acc[mt][nt][1], acc[mt][nt][2], acc[mt][nt][3],
                             a[mt][0], a[mt][1], a[mt][2], a[mt][3],
                             b[nt][0], b[nt][1]);
        }
        __syncthreads();
    }

    const int qrow = lane >> 2;
    const int qcol = (lane & 3) * 2;
#pragma unroll
    for (int mt = 0; mt < 4; mt++) {
        int r0 = block_m + m_off + mt * 16 + qrow;
        int r1 = r0 + 8;
#pragma unroll
        for (int nt = 0; nt < 8; nt++) {
            int col = block_n + n_off + nt * 8 + qcol;
            if (r0 < N_NODES)
                *(float2*)(g_T + (size_t)r0 * TCOLS + col) =
                    make_float2(acc[mt][nt][0], acc[mt][nt][1]);
            if (r1 < N_NODES)
                *(float2*)(g_T + (size_t)r1 * TCOLS + col) =
                    make_float2(acc[mt][nt][2], acc[mt][nt][3]);
        }
    }
}

// ---------------- init agg with conv_bias ----------------
__global__ void init_agg(const float* __restrict__ conv_bias) {
    int i = blockIdx.x * blockDim.x + threadIdx.x;
    if (i < N_NODES * H) g_agg[i] = conv_bias[i & 63];
}

// ---------------- msg: CTA per src node, warp per edge ----------------
__global__ void __launch_bounds__(256) msg_kernel2(const int* __restrict__ dst) {
    int s = blockIdx.x;
    int beg = g_rowptr[s];
    int end = g_rowptr[s + 1];
    if (beg == end) return;
    __shared__ float Ts[TCOLS];
    __shared__ float Bs[64];
    int tid = threadIdx.x;
    const float4* Trow = (const float4*)(g_T + (size_t)s * TCOLS);
    float4* Ts4 = (float4*)Ts;
#pragma unroll
    for (int i = 0; i < 8; i++) Ts4[tid + i * 256] = Trow[tid + i * 256];
    if (tid < 64) Bs[tid] = g_B[s * 64 + tid];
    __syncthreads();

    int wid = tid >> 5;
    int lane = tid & 31;
    const float2* T2 = (const float2*)Ts;
    for (int ei = beg + wid; ei < end; ei += 8) {
        int e = g_eidx[ei];
        int d = dst[e];
        const float* h1 = g_h1f + (size_t)e * EH;
        float ha = h1[lane];
        float hb = h1[lane + 32];
        float hc = h1[lane + 64];
        float hd = h1[lane + 96];
        float m0 = Bs[2 * lane];
        float m1 = Bs[2 * lane + 1];
#pragma unroll
        for (int i = 0; i < 32; i++) {
            float hk = __shfl_sync(0xffffffffu, ha, i);
            float2 t = T2[i * 32 + lane];
            m0 += hk * t.x; m1 += hk * t.y;
        }
#pragma unroll
        for (int i = 0; i < 32; i++) {
            float hk = __shfl_sync(0xffffffffu, hb, i);
            float2 t = T2[(32 + i) * 32 + lane];
            m0 += hk * t.x; m1 += hk * t.y;
        }
#pragma unroll
        for (int i = 0; i < 32; i++) {
            float hk = __shfl_sync(0xffffffffu, hc, i);
            float2 t = T2[(64 + i) * 32 + lane];
            m0 += hk * t.x; m1 += hk * t.y;
        }
#pragma unroll
        for (int i = 0; i < 32; i++) {
            float hk = __shfl_sync(0xffffffffu, hd, i);
            float2 t = T2[(96 + i) * 32 + lane];
            m0 += hk * t.x; m1 += hk * t.y;
        }
        atomicAdd(&g_agg[d * H + 2 * lane], m0);
        atomicAdd(&g_agg[d * H + 2 * lane + 1], m1);
    }
}

// ---------------- relu step (also refresh x-split) ----------------
__global__ void relu_step() {
    int i = blockIdx.x * blockDim.x + threadIdx.x;
    if (i >= N_NODES * H) return;
    float v = fmaxf(g_agg[i], 0.0f);
    g_x[i] = v;
    split_store(v, g_xc + (i >> 6) * KC2, i & 63);
}

// ---------------- BatchNorm ----------------
__global__ void bn_zero() {
    int t = threadIdx.x;
    if (t < H) { g_sum[t] = 0.f; g_sumsq[t] = 0.f; }
}
__global__ void bn_reduce() {
    int t = threadIdx.x;
    int h = t & 63;
    int rsub = t >> 6;
    float s = 0.f, q = 0.f;
    for (int r = blockIdx.x * 4 + rsub; r < N_NODES; r += gridDim.x * 4) {
        float v = g_x[r * H + h];
        s += v;
        q += v * v;
    }
    __shared__ float ss[256], sq[256];
    ss[t] = s;
    sq[t] = q;
    __syncthreads();
    if (t < 64) {
        s = ss[t] + ss[t + 64] + ss[t + 128] + ss[t + 192];
        q = sq[t] + sq[t + 64] + sq[t + 128] + sq[t + 192];
        atomicAdd(&g_sum[h], s);
        atomicAdd(&g_sumsq[h], q);
    }
}
__global__ void bn_apply(const float* __restrict__ gamma, const float* __restrict__ beta,
                         float* __restrict__ out) {
    int i = blockIdx.x * blockDim.x + threadIdx.x;
    if (i >= N_NODES * H) return;
    int h = i & 63;
    float mean = g_sum[h] / (float)N_NODES;
    float var = g_sumsq[h] / (float)N_NODES - mean * mean;
    out[i] = (g_x[i] - mean) * rsqrtf(var + 1e-5f) * gamma[h] + beta[h];
}

// ---------------- launch ----------------
extern "C" void kernel_launch(void* const* d_in, const int* in_sizes, int n_in,
                              void* d_out, int out_size) {
    const float* n_feat    = (const float*)d_in[0];
    const float* e_feat    = (const float*)d_in[1];
    const int*   src       = (const int*)d_in[2];
    const int*   dst       = (const int*)d_in[3];
    const float* W0        = (const float*)d_in[4];
    const float* b0        = (const float*)d_in[5];
    const float* We1       = (const float*)d_in[6];
    const float* be1       = (const float*)d_in[7];
    const float* We2       = (const float*)d_in[8];
    const float* be2       = (const float*)d_in[9];
    const float* conv_bias = (const float*)d_in[10];
    const float* gamma     = (const float*)d_in[11];
    const float* beta      = (const float*)d_in[12];
    float* out = (float*)d_out;

    cudaFuncSetAttribute(tgemm, cudaFuncAttributeMaxDynamicSharedMemorySize, TG_SMEM);

    // one-time prep
    node_mlp<<<N_NODES, 64>>>(n_feat, W0, b0);
    edge_h1<<<(N_EDGES * EH) / 256, 256>>>(e_feat, We1, be1);
    wt_prep<<<(TCOLS * 64) / 256, 256>>>(We2);
    zero_bins<<<(N_NODES + 255) / 256, 256>>>();
    hist_kernel<<<(N_EDGES + 255) / 256, 256>>>(src);
    scan_kernel<<<1, 1024>>>();
    scatter_kernel<<<(N_EDGES + 255) / 256, 256>>>(src);

    int nh = N_NODES * H;
    dim3 tgrid(TCOLS / 128, (N_NODES + 127) / 128);
    for (int step = 0; step < STEPS; step++) {
        b_term<<<N_NODES, 64>>>(be2);
        tgemm<<<tgrid, 128, TG_SMEM>>>();
        init_agg<<<(nh + 255) / 256, 256>>>(conv_bias);
        msg_kernel2<<<N_NODES, 256>>>(dst);
        relu_step<<<(nh + 255) / 256, 256>>>();
    }

    bn_zero<<<1, 64>>>();
    bn_reduce<<<100, 256>>>();
    bn_apply<<<(nh + 255) / 256, 256>>>(gamma, beta, out);
    (void)in_sizes; (void)n_in; (void)out_size;
}

// round 8
// speedup vs baseline: 3.8908x; 1.1381x over previous
#include <cuda_runtime.h>
#include <cuda_bf16.h>
#include <cstdint>

#define N_NODES 10000
#define N_EDGES 100000
#define DIN 64
#define H 64
#define EIN 16
#define EH 128
#define STEPS 3
#define KC2 192          // split-concat K for T-GEMM (64*3)
#define TCOLS 8192       // 128*64

// ---------------- device scratch ----------------
__device__ float g_x[N_NODES * H];
__device__ __nv_bfloat16 g_xc[N_NODES * KC2];     // x split [hi|hi|lo]
__device__ float g_agg[N_NODES * H];
__device__ float g_h1f[(size_t)N_EDGES * EH];     // edge hidden, fp32
__device__ __nv_bfloat16 g_WtC[TCOLS * KC2];      // W'[col][j] split [hi|lo|hi]
__device__ float g_T[(size_t)N_NODES * TCOLS];    // 327 MB
__device__ float g_B[N_NODES * H];
__device__ int g_cnt[N_NODES];
__device__ int g_fill[N_NODES];
__device__ int g_rowptr[N_NODES + 1];
__device__ int g_eidx[N_EDGES];
__device__ float g_sum[H];
__device__ float g_sumsq[H];

// ---------------- helpers ----------------
__device__ __forceinline__ uint32_t smem_u32(const void* p) {
    uint32_t a;
    asm("{ .reg .u64 t; cvta.to.shared.u64 t, %1; cvt.u32.u64 %0, t; }" : "=r"(a) : "l"(p));
    return a;
}
__device__ __forceinline__ void cp_async16(uint32_t dst, const void* src, int src_bytes) {
    asm volatile("cp.async.cg.shared.global [%0], [%1], 16, %2;"
                 :: "r"(dst), "l"(src), "r"(src_bytes));
}
#define CP_COMMIT() asm volatile("cp.async.commit_group;" ::: "memory")
#define CP_WAIT(n)  asm volatile("cp.async.wait_group %0;" :: "n"(n) : "memory")

__device__ __forceinline__ void ldsm_x4(uint32_t& r0, uint32_t& r1, uint32_t& r2,
                                        uint32_t& r3, uint32_t addr) {
    asm volatile("ldmatrix.sync.aligned.m8n8.x4.shared.b16 {%0,%1,%2,%3}, [%4];"
                 : "=r"(r0), "=r"(r1), "=r"(r2), "=r"(r3) : "r"(addr));
}
__device__ __forceinline__ void mma_bf16(float& c0, float& c1, float& c2, float& c3,
                                         uint32_t a0, uint32_t a1, uint32_t a2, uint32_t a3,
                                         uint32_t b0, uint32_t b1) {
    asm volatile(
        "mma.sync.aligned.m16n8k16.row.col.f32.bf16.bf16.f32 "
        "{%0,%1,%2,%3}, {%4,%5,%6,%7}, {%8,%9}, {%0,%1,%2,%3};"
        : "+f"(c0), "+f"(c1), "+f"(c2), "+f"(c3)
        : "r"(a0), "r"(a1), "r"(a2), "r"(a3), "r"(b0), "r"(b1));
}
__device__ __forceinline__ void split_store(float v, __nv_bfloat16* row, int j) {
    __nv_bfloat16 hi = __float2bfloat16(v);
    __nv_bfloat16 lo = __float2bfloat16(v - __bfloat162float(hi));
    row[j] = hi;
    row[64 + j] = hi;
    row[128 + j] = lo;
}

// ---------------- node MLP (writes x and x-split) ----------------
__global__ void node_mlp(const float* __restrict__ nf, const float* __restrict__ W0,
                         const float* __restrict__ b0) {
    int n = blockIdx.x;
    int h = threadIdx.x;
    __shared__ float xs[DIN];
    xs[h] = nf[n * DIN + h];
    __syncthreads();
    float acc = b0[h];
#pragma unroll
    for (int i = 0; i < DIN; i++) acc += xs[i] * W0[i * H + h];
    float v = fmaxf(acc, 0.0f);
    g_x[n * H + h] = v;
    split_store(v, g_xc + n * KC2, h);
}

// ---------------- edge hidden (fp32) ----------------
__global__ void edge_h1(const float* __restrict__ ef, const float* __restrict__ We1,
                        const float* __restrict__ be1) {
    int gid = blockIdx.x * blockDim.x + threadIdx.x;
    int e = gid >> 7;
    int k = gid & 127;
    if (e >= N_EDGES) return;
    float acc = be1[k];
#pragma unroll
    for (int i = 0; i < EIN; i++) acc += ef[e * EIN + i] * We1[i * EH + k];
    g_h1f[gid] = fmaxf(acc, 0.0f);
}

// ---------------- W' prep: W'[col=k*64+o][j] = We2[k][j*64+o], split [hi|lo|hi] ----------------
__global__ void wt_prep(const float* __restrict__ We2) {
    int idx = blockIdx.x * blockDim.x + threadIdx.x;  // TCOLS*64
    if (idx >= TCOLS * 64) return;
    int col = idx >> 6;
    int j = idx & 63;
    int k = col >> 6;
    int o = col & 63;
    float v = We2[k * 4096 + j * 64 + o];
    __nv_bfloat16 hi = __float2bfloat16(v);
    __nv_bfloat16 lo = __float2bfloat16(v - __bfloat162float(hi));
    __nv_bfloat16* row = g_WtC + col * KC2;
    row[j] = hi;
    row[64 + j] = lo;
    row[128 + j] = hi;
}

// ---------------- edge sort by src: hist / scan / scatter ----------------
__global__ void zero_bins() {
    int i = blockIdx.x * blockDim.x + threadIdx.x;
    if (i < N_NODES) { g_cnt[i] = 0; g_fill[i] = 0; }
}
__global__ void hist_kernel(const int* __restrict__ src) {
    int e = blockIdx.x * blockDim.x + threadIdx.x;
    if (e < N_EDGES) atomicAdd(&g_cnt[src[e]], 1);
}
__global__ void scan_kernel() {
    __shared__ int ts[1024];
    int t = threadIdx.x;
    int base = t * 10;
    int c[10];
    int tot = 0;
#pragma unroll
    for (int i = 0; i < 10; i++) {
        int idx = base + i;
        c[i] = (idx < N_NODES) ? g_cnt[idx] : 0;
        tot += c[i];
    }
    ts[t] = tot;
    __syncthreads();
    for (int off = 1; off < 1024; off <<= 1) {
        int v = (t >= off) ? ts[t - off] : 0;
        __syncthreads();
        ts[t] += v;
        __syncthreads();
    }
    int run = ts[t] - tot;  // exclusive prefix
#pragma unroll
    for (int i = 0; i < 10; i++) {
        int idx = base + i;
        if (idx < N_NODES) { g_rowptr[idx] = run; run += c[i]; }
    }
    if (t == 1023) g_rowptr[N_NODES] = N_EDGES;
}
__global__ void scatter_kernel(const int* __restrict__ src) {
    int e = blockIdx.x * blockDim.x + threadIdx.x;
    if (e >= N_EDGES) return;
    int s = src[e];
    int pos = g_rowptr[s] + atomicAdd(&g_fill[s], 1);
    g_eidx[pos] = e;
}

// ---------------- per-step: B[n,o] = sum_j x[n,j]*be2[j*64+o] ----------------
__global__ void b_term(const float* __restrict__ be2) {
    int n = blockIdx.x;
    int o = threadIdx.x;
    __shared__ float xs[64];
    xs[o] = g_x[n * 64 + o];
    __syncthreads();
    float acc = 0.f;
#pragma unroll
    for (int j = 0; j < 64; j++) acc += xs[j] * be2[j * 64 + o];
    g_B[n * 64 + o] = acc;
}

// ---------------- T-GEMM: T[n, col] = xc[n] . WtC[col], M=10000 N=8192 K=192 ----------------
#define BKT 64
#define STAGE_BYTES 32768
#define TG_SMEM (3 * STAGE_BYTES)
#define NKT2 3

__global__ void __launch_bounds__(128, 2) tgemm() {
    extern __shared__ char smem[];
    const uint32_t sbase = smem_u32(smem);
    const int tid = threadIdx.x;
    const int wid = tid >> 5;
    const int lane = tid & 31;
    const int block_n = blockIdx.x * 128;
    const int block_m = blockIdx.y * 128;

    const int wm = wid & 1;
    const int wn = wid >> 1;
    const int m_off = wm * 64;
    const int n_off = wn * 64;

    float acc[4][8][4];
#pragma unroll
    for (int mt = 0; mt < 4; mt++)
#pragma unroll
        for (int nt = 0; nt < 8; nt++)
#pragma unroll
            for (int q = 0; q < 4; q++) acc[mt][nt][q] = 0.0f;

    auto load_stage = [&](int stage, int kt) {
        const int k0 = kt * BKT;
        const uint32_t As = sbase + stage * STAGE_BYTES;
        const uint32_t Bs = As + 16384;
#pragma unroll
        for (int i = 0; i < 8; i++) {
            int cid = tid + i * 128;
            int r = cid >> 3;
            int c = cid & 7;
            int n = block_m + r;
            const void* gsrc = g_xc + (size_t)n * KC2 + k0 + c * 8;
            uint32_t sdst = As + r * 128 + ((c ^ (r & 7)) << 4);
            cp_async16(sdst, gsrc, (n < N_NODES) ? 16 : 0);
        }
#pragma unroll
        for (int i = 0; i < 8; i++) {
            int cid = tid + i * 128;
            int r = cid >> 3;
            int c = cid & 7;
            int col = block_n + r;
            const void* gsrc = g_WtC + (size_t)col * KC2 + k0 + c * 8;
            uint32_t sdst = Bs + r * 128 + ((c ^ (r & 7)) << 4);
            cp_async16(sdst, gsrc, 16);
        }
    };

    const int a_row_l = lane & 15;
    const int a_uoff = lane >> 4;
    const int b_row_l = ((lane >> 4) << 3) + (lane & 7);
    const int b_uoff = (lane >> 3) & 1;

    load_stage(0, 0);
    CP_COMMIT();
    load_stage(1, 1);
    CP_COMMIT();

#pragma unroll
    for (int kt = 0; kt < NKT2; kt++) {
        if (kt == NKT2 - 1) { CP_WAIT(0); } else { CP_WAIT(1); }
        __syncthreads();
        if (kt + 2 < NKT2) {
            load_stage(kt + 2, kt + 2);
            CP_COMMIT();
        }
        const uint32_t As = sbase + kt * STAGE_BYTES;
        const uint32_t Bs = As + 16384;
#pragma unroll
        for (int ks = 0; ks < 4; ks++) {
            const int ub = ks * 2;
            uint32_t a[4][4];
#pragma unroll
            for (int mt = 0; mt < 4; mt++) {
                int r = m_off + mt * 16 + a_row_l;
                int u = ub + a_uoff;
                ldsm_x4(a[mt][0], a[mt][1], a[mt][2], a[mt][3],
                        As + r * 128 + ((u ^ (r & 7)) << 4));
            }
            uint32_t b[8][2];
#pragma unroll
            for (int np = 0; np < 4; np++) {
                int r = n_off + np * 16 + b_row_l;
                int u = ub + b_uoff;
                uint32_t r0, r1, r2, r3;
                ldsm_x4(r0, r1, r2, r3, Bs + r * 128 + ((u ^ (r & 7)) << 4));
                b[np * 2][0] = r0; b[np * 2][1] = r1;
                b[np * 2 + 1][0] = r2; b[np * 2 + 1][1] = r3;
            }
#pragma unroll
            for (int mt = 0; mt < 4; mt++)
#pragma unroll
                for (int nt = 0; nt < 8; nt++)
                    mma_bf16(acc[mt][nt][0], acc[mt][nt][1], acc[mt][nt][2], acc[mt][nt][3],
                             a[mt][0], a[mt][1], a[mt][2], a[mt][3],
                             b[nt][0], b[nt][1]);
        }
        __syncthreads();
    }

    const int qrow = lane >> 2;
    const int qcol = (lane & 3) * 2;
#pragma unroll
    for (int mt = 0; mt < 4; mt++) {
        int r0 = block_m + m_off + mt * 16 + qrow;
        int r1 = r0 + 8;
#pragma unroll
        for (int nt = 0; nt < 8; nt++) {
            int col = block_n + n_off + nt * 8 + qcol;
            if (r0 < N_NODES)
                *(float2*)(g_T + (size_t)r0 * TCOLS + col) =
                    make_float2(acc[mt][nt][0], acc[mt][nt][1]);
            if (r1 < N_NODES)
                *(float2*)(g_T + (size_t)r1 * TCOLS + col) =
                    make_float2(acc[mt][nt][2], acc[mt][nt][3]);
        }
    }
}

// ---------------- init agg with conv_bias ----------------
__global__ void init_agg(const float* __restrict__ conv_bias) {
    int i = blockIdx.x * blockDim.x + threadIdx.x;
    if (i < N_NODES * H) g_agg[i] = conv_bias[i & 63];
}

// ---------------- msg: CTA per src node, 4 edges per warp (T reused 4x) ----------------
__global__ void __launch_bounds__(256) msg_kernel2(const int* __restrict__ dst) {
    int s = blockIdx.x;
    int beg = g_rowptr[s];
    int end = g_rowptr[s + 1];
    if (beg == end) return;
    __shared__ float Ts[TCOLS];
    __shared__ float Bs[64];
    int tid = threadIdx.x;
    const float4* Trow = (const float4*)(g_T + (size_t)s * TCOLS);
    float4* Ts4 = (float4*)Ts;
#pragma unroll
    for (int i = 0; i < 8; i++) Ts4[tid + i * 256] = Trow[tid + i * 256];
    if (tid < 64) Bs[tid] = g_B[s * 64 + tid];
    __syncthreads();

    int wid = tid >> 5;
    int lane = tid & 31;
    const float2* T2 = (const float2*)Ts;
    float b0v = Bs[2 * lane];
    float b1v = Bs[2 * lane + 1];

    for (int base = beg + wid * 4; base < end; base += 32) {
        int ne = end - base;
        if (ne > 4) ne = 4;
        int d[4];
        float ha[4], hb[4], hc[4], hd[4], m0[4], m1[4];
#pragma unroll
        for (int j = 0; j < 4; j++) {
            ha[j] = hb[j] = hc[j] = hd[j] = 0.f;
            m0[j] = b0v;
            m1[j] = b1v;
            d[j] = 0;
        }
#pragma unroll
        for (int j = 0; j < 4; j++) {
            if (j < ne) {
                int e = g_eidx[base + j];
                d[j] = dst[e];
                const float* h1 = g_h1f + (size_t)e * EH;
                ha[j] = h1[lane];
                hb[j] = h1[lane + 32];
                hc[j] = h1[lane + 64];
                hd[j] = h1[lane + 96];
            }
        }
#pragma unroll
        for (int i = 0; i < 32; i++) {
            float2 t = T2[i * 32 + lane];
#pragma unroll
            for (int j = 0; j < 4; j++) {
                float hk = __shfl_sync(0xffffffffu, ha[j], i);
                m0[j] += hk * t.x;
                m1[j] += hk * t.y;
            }
        }
#pragma unroll
        for (int i = 0; i < 32; i++) {
            float2 t = T2[(32 + i) * 32 + lane];
#pragma unroll
            for (int j = 0; j < 4; j++) {
                float hk = __shfl_sync(0xffffffffu, hb[j], i);
                m0[j] += hk * t.x;
                m1[j] += hk * t.y;
            }
        }
#pragma unroll
        for (int i = 0; i < 32; i++) {
            float2 t = T2[(64 + i) * 32 + lane];
#pragma unroll
            for (int j = 0; j < 4; j++) {
                float hk = __shfl_sync(0xffffffffu, hc[j], i);
                m0[j] += hk * t.x;
                m1[j] += hk * t.y;
            }
        }
#pragma unroll
        for (int i = 0; i < 32; i++) {
            float2 t = T2[(96 + i) * 32 + lane];
#pragma unroll
            for (int j = 0; j < 4; j++) {
                float hk = __shfl_sync(0xffffffffu, hd[j], i);
                m0[j] += hk * t.x;
                m1[j] += hk * t.y;
            }
        }
#pragma unroll
        for (int j = 0; j < 4; j++) {
            if (j < ne) {
                atomicAdd(&g_agg[d[j] * H + 2 * lane], m0[j]);
                atomicAdd(&g_agg[d[j] * H + 2 * lane + 1], m1[j]);
            }
        }
    }
}

// ---------------- relu step (also refresh x-split) ----------------
__global__ void relu_step() {
    int i = blockIdx.x * blockDim.x + threadIdx.x;
    if (i >= N_NODES * H) return;
    float v = fmaxf(g_agg[i], 0.0f);
    g_x[i] = v;
    split_store(v, g_xc + (i >> 6) * KC2, i & 63);
}

// ---------------- BatchNorm ----------------
__global__ void bn_zero() {
    int t = threadIdx.x;
    if (t < H) { g_sum[t] = 0.f; g_sumsq[t] = 0.f; }
}
__global__ void bn_reduce() {
    int t = threadIdx.x;
    int h = t & 63;
    int rsub = t >> 6;
    float s = 0.f, q = 0.f;
    for (int r = blockIdx.x * 4 + rsub; r < N_NODES; r += gridDim.x * 4) {
        float v = g_x[r * H + h];
        s += v;
        q += v * v;
    }
    __shared__ float ss[256], sq[256];
    ss[t] = s;
    sq[t] = q;
    __syncthreads();
    if (t < 64) {
        s = ss[t] + ss[t + 64] + ss[t + 128] + ss[t + 192];
        q = sq[t] + sq[t + 64] + sq[t + 128] + sq[t + 192];
        atomicAdd(&g_sum[h], s);
        atomicAdd(&g_sumsq[h], q);
    }
}
__global__ void bn_apply(const float* __restrict__ gamma, const float* __restrict__ beta,
                         float* __restrict__ out) {
    int i = blockIdx.x * blockDim.x + threadIdx.x;
    if (i >= N_NODES * H) return;
    int h = i & 63;
    float mean = g_sum[h] / (float)N_NODES;
    float var = g_sumsq[h] / (float)N_NODES - mean * mean;
    out[i] = (g_x[i] - mean) * rsqrtf(var + 1e-5f) * gamma[h] + beta[h];
}

// ---------------- launch ----------------
extern "C" void kernel_launch(void* const* d_in, const int* in_sizes, int n_in,
                              void* d_out, int out_size) {
    const float* n_feat    = (const float*)d_in[0];
    const float* e_feat    = (const float*)d_in[1];
    const int*   src       = (const int*)d_in[2];
    const int*   dst       = (const int*)d_in[3];
    const float* W0        = (const float*)d_in[4];
    const float* b0        = (const float*)d_in[5];
    const float* We1       = (const float*)d_in[6];
    const float* be1       = (const float*)d_in[7];
    const float* We2       = (const float*)d_in[8];
    const float* be2       = (const float*)d_in[9];
    const float* conv_bias = (const float*)d_in[10];
    const float* gamma     = (const float*)d_in[11];
    const float* beta      = (const float*)d_in[12];
    float* out = (float*)d_out;

    cudaFuncSetAttribute(tgemm, cudaFuncAttributeMaxDynamicSharedMemorySize, TG_SMEM);

    // one-time prep
    node_mlp<<<N_NODES, 64>>>(n_feat, W0, b0);
    edge_h1<<<(N_EDGES * EH) / 256, 256>>>(e_feat, We1, be1);
    wt_prep<<<(TCOLS * 64) / 256, 256>>>(We2);
    zero_bins<<<(N_NODES + 255) / 256, 256>>>();
    hist_kernel<<<(N_EDGES + 255) / 256, 256>>>(src);
    scan_kernel<<<1, 1024>>>();
    scatter_kernel<<<(N_EDGES + 255) / 256, 256>>>(src);

    int nh = N_NODES * H;
    dim3 tgrid(TCOLS / 128, (N_NODES + 127) / 128);
    for (int step = 0; step < STEPS; step++) {
        b_term<<<N_NODES, 64>>>(be2);
        tgemm<<<tgrid, 128, TG_SMEM>>>();
        init_agg<<<(nh + 255) / 256, 256>>>(conv_bias);
        msg_kernel2<<<N_NODES, 256>>>(dst);
        relu_step<<<(nh + 255) / 256, 256>>>();
    }

    bn_zero<<<1, 64>>>();
    bn_reduce<<<100, 256>>>();
    bn_apply<<<(nh + 255) / 256, 256>>>(gamma, beta, out);
    (void)in_sizes; (void)n_in; (void)out_size;
}

// round 9
// speedup vs baseline: 3.9881x; 1.0250x over previous
#include <cuda_runtime.h>
#include <cuda_bf16.h>
#include <cuda_fp16.h>
#include <cstdint>

#define N_NODES 10000
#define N_EDGES 100000
#define DIN 64
#define H 64
#define EIN 16
#define EH 128
#define STEPS 3
#define KC2 192          // split-concat K for T-GEMM (64*3)
#define TCOLS 8192       // 128*64

// ---------------- device scratch ----------------
__device__ float g_x[N_NODES * H];
__device__ __nv_bfloat16 g_xc[N_NODES * KC2];     // x split [hi|hi|lo]
__device__ float g_agg[N_NODES * H];
__device__ float g_h1f[(size_t)N_EDGES * EH];     // edge hidden, fp32
__device__ __nv_bfloat16 g_WtC[TCOLS * KC2];      // W'[col][j] split [hi|lo|hi]
__device__ __half g_T[(size_t)N_NODES * TCOLS];   // 163 MB fp16
__device__ float g_B[N_NODES * H];
__device__ int g_cnt[N_NODES];
__device__ int g_fill[N_NODES];
__device__ int g_rowptr[N_NODES + 1];
__device__ int g_eidx[N_EDGES];
__device__ float g_sum[H];
__device__ float g_sumsq[H];

// ---------------- helpers ----------------
__device__ __forceinline__ uint32_t smem_u32(const void* p) {
    uint32_t a;
    asm("{ .reg .u64 t; cvta.to.shared.u64 t, %1; cvt.u32.u64 %0, t; }" : "=r"(a) : "l"(p));
    return a;
}
__device__ __forceinline__ void cp_async16(uint32_t dst, const void* src, int src_bytes) {
    asm volatile("cp.async.cg.shared.global [%0], [%1], 16, %2;"
                 :: "r"(dst), "l"(src), "r"(src_bytes));
}
#define CP_COMMIT() asm volatile("cp.async.commit_group;" ::: "memory")
#define CP_WAIT(n)  asm volatile("cp.async.wait_group %0;" :: "n"(n) : "memory")

__device__ __forceinline__ void ldsm_x4(uint32_t& r0, uint32_t& r1, uint32_t& r2,
                                        uint32_t& r3, uint32_t addr) {
    asm volatile("ldmatrix.sync.aligned.m8n8.x4.shared.b16 {%0,%1,%2,%3}, [%4];"
                 : "=r"(r0), "=r"(r1), "=r"(r2), "=r"(r3) : "r"(addr));
}
__device__ __forceinline__ void mma_bf16(float& c0, float& c1, float& c2, float& c3,
                                         uint32_t a0, uint32_t a1, uint32_t a2, uint32_t a3,
                                         uint32_t b0, uint32_t b1) {
    asm volatile(
        "mma.sync.aligned.m16n8k16.row.col.f32.bf16.bf16.f32 "
        "{%0,%1,%2,%3}, {%4,%5,%6,%7}, {%8,%9}, {%0,%1,%2,%3};"
        : "+f"(c0), "+f"(c1), "+f"(c2), "+f"(c3)
        : "r"(a0), "r"(a1), "r"(a2), "r"(a3), "r"(b0), "r"(b1));
}
__device__ __forceinline__ void split_store(float v, __nv_bfloat16* row, int j) {
    __nv_bfloat16 hi = __float2bfloat16(v);
    __nv_bfloat16 lo = __float2bfloat16(v - __bfloat162float(hi));
    row[j] = hi;
    row[64 + j] = hi;
    row[128 + j] = lo;
}

// ---------------- node MLP (writes x, x-split, and B for step 0) ----------------
__global__ void node_mlp(const float* __restrict__ nf, const float* __restrict__ W0,
                         const float* __restrict__ b0, const float* __restrict__ be2) {
    int n = blockIdx.x;
    int h = threadIdx.x;
    __shared__ float xs[DIN];
    __shared__ float vs[64];
    xs[h] = nf[n * DIN + h];
    __syncthreads();
    float acc = b0[h];
#pragma unroll
    for (int i = 0; i < DIN; i++) acc += xs[i] * W0[i * H + h];
    float v = fmaxf(acc, 0.0f);
    g_x[n * H + h] = v;
    split_store(v, g_xc + n * KC2, h);
    vs[h] = v;
    __syncthreads();
    float accB = 0.f;
#pragma unroll
    for (int j = 0; j < 64; j++) accB += vs[j] * be2[j * 64 + h];
    g_B[n * 64 + h] = accB;
}

// ---------------- edge hidden (fp32) ----------------
__global__ void edge_h1(const float* __restrict__ ef, const float* __restrict__ We1,
                        const float* __restrict__ be1) {
    int gid = blockIdx.x * blockDim.x + threadIdx.x;
    int e = gid >> 7;
    int k = gid & 127;
    if (e >= N_EDGES) return;
    float acc = be1[k];
#pragma unroll
    for (int i = 0; i < EIN; i++) acc += ef[e * EIN + i] * We1[i * EH + k];
    g_h1f[gid] = fmaxf(acc, 0.0f);
}

// ---------------- W' prep: W'[col=k*64+o][j] = We2[k][j*64+o], split [hi|lo|hi] ----------------
__global__ void wt_prep(const float* __restrict__ We2) {
    int idx = blockIdx.x * blockDim.x + threadIdx.x;  // TCOLS*64
    if (idx >= TCOLS * 64) return;
    int col = idx >> 6;
    int j = idx & 63;
    int k = col >> 6;
    int o = col & 63;
    float v = We2[k * 4096 + j * 64 + o];
    __nv_bfloat16 hi = __float2bfloat16(v);
    __nv_bfloat16 lo = __float2bfloat16(v - __bfloat162float(hi));
    __nv_bfloat16* row = g_WtC + col * KC2;
    row[j] = hi;
    row[64 + j] = lo;
    row[128 + j] = hi;
}

// ---------------- edge sort by src: hist / scan / scatter ----------------
__global__ void zero_bins() {
    int i = blockIdx.x * blockDim.x + threadIdx.x;
    if (i < N_NODES) { g_cnt[i] = 0; g_fill[i] = 0; }
}
__global__ void hist_kernel(const int* __restrict__ src) {
    int e = blockIdx.x * blockDim.x + threadIdx.x;
    if (e < N_EDGES) atomicAdd(&g_cnt[src[e]], 1);
}
__global__ void scan_kernel() {
    __shared__ int ts[1024];
    int t = threadIdx.x;
    int base = t * 10;
    int c[10];
    int tot = 0;
#pragma unroll
    for (int i = 0; i < 10; i++) {
        int idx = base + i;
        c[i] = (idx < N_NODES) ? g_cnt[idx] : 0;
        tot += c[i];
    }
    ts[t] = tot;
    __syncthreads();
    for (int off = 1; off < 1024; off <<= 1) {
        int v = (t >= off) ? ts[t - off] : 0;
        __syncthreads();
        ts[t] += v;
        __syncthreads();
    }
    int run = ts[t] - tot;  // exclusive prefix
#pragma unroll
    for (int i = 0; i < 10; i++) {
        int idx = base + i;
        if (idx < N_NODES) { g_rowptr[idx] = run; run += c[i]; }
    }
    if (t == 1023) g_rowptr[N_NODES] = N_EDGES;
}
__global__ void scatter_kernel(const int* __restrict__ src) {
    int e = blockIdx.x * blockDim.x + threadIdx.x;
    if (e >= N_EDGES) return;
    int s = src[e];
    int pos = g_rowptr[s] + atomicAdd(&g_fill[s], 1);
    g_eidx[pos] = e;
}

// ---------------- T-GEMM: T[n, col] = xc[n] . WtC[col], M=10000 N=8192 K=192 ----------------
#define BKT 64
#define STAGE_BYTES 32768
#define TG_SMEM (3 * STAGE_BYTES)
#define NKT2 3

__global__ void __launch_bounds__(128, 2) tgemm() {
    extern __shared__ char smem[];
    const uint32_t sbase = smem_u32(smem);
    const int tid = threadIdx.x;
    const int wid = tid >> 5;
    const int lane = tid & 31;
    const int block_n = blockIdx.x * 128;
    const int block_m = blockIdx.y * 128;

    const int wm = wid & 1;
    const int wn = wid >> 1;
    const int m_off = wm * 64;
    const int n_off = wn * 64;

    float acc[4][8][4];
#pragma unroll
    for (int mt = 0; mt < 4; mt++)
#pragma unroll
        for (int nt = 0; nt < 8; nt++)
#pragma unroll
            for (int q = 0; q < 4; q++) acc[mt][nt][q] = 0.0f;

    auto load_stage = [&](int stage, int kt) {
        const int k0 = kt * BKT;
        const uint32_t As = sbase + stage * STAGE_BYTES;
        const uint32_t Bs = As + 16384;
#pragma unroll
        for (int i = 0; i < 8; i++) {
            int cid = tid + i * 128;
            int r = cid >> 3;
            int c = cid & 7;
            int n = block_m + r;
            const void* gsrc = g_xc + (size_t)n * KC2 + k0 + c * 8;
            uint32_t sdst = As + r * 128 + ((c ^ (r & 7)) << 4);
            cp_async16(sdst, gsrc, (n < N_NODES) ? 16 : 0);
        }
#pragma unroll
        for (int i = 0; i < 8; i++) {
            int cid = tid + i * 128;
            int r = cid >> 3;
            int c = cid & 7;
            int col = block_n + r;
            const void* gsrc = g_WtC + (size_t)col * KC2 + k0 + c * 8;
            uint32_t sdst = Bs + r * 128 + ((c ^ (r & 7)) << 4);
            cp_async16(sdst, gsrc, 16);
        }
    };

    const int a_row_l = lane & 15;
    const int a_uoff = lane >> 4;
    const int b_row_l = ((lane >> 4) << 3) + (lane & 7);
    const int b_uoff = (lane >> 3) & 1;

    load_stage(0, 0);
    CP_COMMIT();
    load_stage(1, 1);
    CP_COMMIT();

#pragma unroll
    for (int kt = 0; kt < NKT2; kt++) {
        if (kt == NKT2 - 1) { CP_WAIT(0); } else { CP_WAIT(1); }
        __syncthreads();
        if (kt + 2 < NKT2) {
            load_stage(kt + 2, kt + 2);
            CP_COMMIT();
        }
        const uint32_t As = sbase + kt * STAGE_BYTES;
        const uint32_t Bs = As + 16384;
#pragma unroll
        for (int ks = 0; ks < 4; ks++) {
            const int ub = ks * 2;
            uint32_t a[4][4];
#pragma unroll
            for (int mt = 0; mt < 4; mt++) {
                int r = m_off + mt * 16 + a_row_l;
                int u = ub + a_uoff;
                ldsm_x4(a[mt][0], a[mt][1], a[mt][2], a[mt][3],
                        As + r * 128 + ((u ^ (r & 7)) << 4));
            }
            uint32_t b[8][2];
#pragma unroll
            for (int np = 0; np < 4; np++) {
                int r = n_off + np * 16 + b_row_l;
                int u = ub + b_uoff;
                uint32_t r0, r1, r2, r3;
                ldsm_x4(r0, r1, r2, r3, Bs + r * 128 + ((u ^ (r & 7)) << 4));
                b[np * 2][0] = r0; b[np * 2][1] = r1;
                b[np * 2 + 1][0] = r2; b[np * 2 + 1][1] = r3;
            }
#pragma unroll
            for (int mt = 0; mt < 4; mt++)
#pragma unroll
                for (int nt = 0; nt < 8; nt++)
                    mma_bf16(acc[mt][nt][0], acc[mt][nt][1], acc[mt][nt][2], acc[mt][nt][3],
                             a[mt][0], a[mt][1], a[mt][2], a[mt][3],
                             b[nt][0], b[nt][1]);
        }
        __syncthreads();
    }

    const int qrow = lane >> 2;
    const int qcol = (lane & 3) * 2;
#pragma unroll
    for (int mt = 0; mt < 4; mt++) {
        int r0 = block_m + m_off + mt * 16 + qrow;
        int r1 = r0 + 8;
#pragma unroll
        for (int nt = 0; nt < 8; nt++) {
            int col = block_n + n_off + nt * 8 + qcol;
            if (r0 < N_NODES)
                *(__half2*)(g_T + (size_t)r0 * TCOLS + col) =
                    __floats2half2_rn(acc[mt][nt][0], acc[mt][nt][1]);
            if (r1 < N_NODES)
                *(__half2*)(g_T + (size_t)r1 * TCOLS + col) =
                    __floats2half2_rn(acc[mt][nt][2], acc[mt][nt][3]);
        }
    }
}

// ---------------- init agg with conv_bias ----------------
__global__ void init_agg(const float* __restrict__ conv_bias) {
    int i = blockIdx.x * blockDim.x + threadIdx.x;
    if (i < N_NODES * H) g_agg[i] = conv_bias[i & 63];
}

// ---------------- msg: CTA per src node, 4 edges per warp (T reused 4x) ----------------
__global__ void __launch_bounds__(256) msg_kernel2(const int* __restrict__ dst) {
    int s = blockIdx.x;
    int beg = g_rowptr[s];
    int end = g_rowptr[s + 1];
    if (beg == end) return;
    __shared__ float Ts[TCOLS];
    __shared__ float Bs[64];
    int tid = threadIdx.x;
    const uint4* Trow4 = (const uint4*)(g_T + (size_t)s * TCOLS);  // 1024 uint4 (8 halves)
    float4* Ts4 = (float4*)Ts;
#pragma unroll
    for (int i = 0; i < 4; i++) {
        int idx = tid + i * 256;
        uint4 v = Trow4[idx];
        const __half2* hp = (const __half2*)&v;
        float2 f0 = __half22float2(hp[0]);
        float2 f1 = __half22float2(hp[1]);
        float2 f2 = __half22float2(hp[2]);
        float2 f3 = __half22float2(hp[3]);
        Ts4[idx * 2 + 0] = make_float4(f0.x, f0.y, f1.x, f1.y);
        Ts4[idx * 2 + 1] = make_float4(f2.x, f2.y, f3.x, f3.y);
    }
    if (tid < 64) Bs[tid] = g_B[s * 64 + tid];
    __syncthreads();

    int wid = tid >> 5;
    int lane = tid & 31;
    const float2* T2 = (const float2*)Ts;
    float b0v = Bs[2 * lane];
    float b1v = Bs[2 * lane + 1];

    for (int base = beg + wid * 4; base < end; base += 32) {
        int ne = end - base;
        if (ne > 4) ne = 4;
        int d[4];
        float ha[4], hb[4], hc[4], hd[4], m0[4], m1[4];
#pragma unroll
        for (int j = 0; j < 4; j++) {
            ha[j] = hb[j] = hc[j] = hd[j] = 0.f;
            m0[j] = b0v;
            m1[j] = b1v;
            d[j] = 0;
        }
#pragma unroll
        for (int j = 0; j < 4; j++) {
            if (j < ne) {
                int e = g_eidx[base + j];
                d[j] = dst[e];
                const float* h1 = g_h1f + (size_t)e * EH;
                ha[j] = h1[lane];
                hb[j] = h1[lane + 32];
                hc[j] = h1[lane + 64];
                hd[j] = h1[lane + 96];
            }
        }
#pragma unroll
        for (int i = 0; i < 32; i++) {
            float2 t = T2[i * 32 + lane];
#pragma unroll
            for (int j = 0; j < 4; j++) {
                float hk = __shfl_sync(0xffffffffu, ha[j], i);
                m0[j] += hk * t.x;
                m1[j] += hk * t.y;
            }
        }
#pragma unroll
        for (int i = 0; i < 32; i++) {
            float2 t = T2[(32 + i) * 32 + lane];
#pragma unroll
            for (int j = 0; j < 4; j++) {
                float hk = __shfl_sync(0xffffffffu, hb[j], i);
                m0[j] += hk * t.x;
                m1[j] += hk * t.y;
            }
        }
#pragma unroll
        for (int i = 0; i < 32; i++) {
            float2 t = T2[(64 + i) * 32 + lane];
#pragma unroll
            for (int j = 0; j < 4; j++) {
                float hk = __shfl_sync(0xffffffffu, hc[j], i);
                m0[j] += hk * t.x;
                m1[j] += hk * t.y;
            }
        }
#pragma unroll
        for (int i = 0; i < 32; i++) {
            float2 t = T2[(96 + i) * 32 + lane];
#pragma unroll
            for (int j = 0; j < 4; j++) {
                float hk = __shfl_sync(0xffffffffu, hd[j], i);
                m0[j] += hk * t.x;
                m1[j] += hk * t.y;
            }
        }
#pragma unroll
        for (int j = 0; j < 4; j++) {
            if (j < ne) {
                atomicAdd(&g_agg[d[j] * H + 2 * lane], m0[j]);
                atomicAdd(&g_agg[d[j] * H + 2 * lane + 1], m1[j]);
            }
        }
    }
}

// ---------------- relu step (refresh x, x-split, and B) ----------------
__global__ void relu_step_b(const float* __restrict__ be2) {
    int n = blockIdx.x;
    int o = threadIdx.x;
    __shared__ float xs[64];
    float v = fmaxf(g_agg[n * 64 + o], 0.0f);
    g_x[n * 64 + o] = v;
    split_store(v, g_xc + n * KC2, o);
    xs[o] = v;
    __syncthreads();
    float acc = 0.f;
#pragma unroll
    for (int j = 0; j < 64; j++) acc += xs[j] * be2[j * 64 + o];
    g_B[n * 64 + o] = acc;
}

// ---------------- BatchNorm ----------------
__global__ void bn_zero() {
    int t = threadIdx.x;
    if (t < H) { g_sum[t] = 0.f; g_sumsq[t] = 0.f; }
}
__global__ void bn_reduce() {
    int t = threadIdx.x;
    int h = t & 63;
    int rsub = t >> 6;
    float s = 0.f, q = 0.f;
    for (int r = blockIdx.x * 4 + rsub; r < N_NODES; r += gridDim.x * 4) {
        float v = g_x[r * H + h];
        s += v;
        q += v * v;
    }
    __shared__ float ss[256], sq[256];
    ss[t] = s;
    sq[t] = q;
    __syncthreads();
    if (t < 64) {
        s = ss[t] + ss[t + 64] + ss[t + 128] + ss[t + 192];
        q = sq[t] + sq[t + 64] + sq[t + 128] + sq[t + 192];
        atomicAdd(&g_sum[h], s);
        atomicAdd(&g_sumsq[h], q);
    }
}
__global__ void bn_apply(const float* __restrict__ gamma, const float* __restrict__ beta,
                         float* __restrict__ out) {
    int i = blockIdx.x * blockDim.x + threadIdx.x;
    if (i >= N_NODES * H) return;
    int h = i & 63;
    float mean = g_sum[h] / (float)N_NODES;
    float var = g_sumsq[h] / (float)N_NODES - mean * mean;
    out[i] = (g_x[i] - mean) * rsqrtf(var + 1e-5f) * gamma[h] + beta[h];
}

// ---------------- launch ----------------
extern "C" void kernel_launch(void* const* d_in, const int* in_sizes, int n_in,
                              void* d_out, int out_size) {
    const float* n_feat    = (const float*)d_in[0];
    const float* e_feat    = (const float*)d_in[1];
    const int*   src       = (const int*)d_in[2];
    const int*   dst       = (const int*)d_in[3];
    const float* W0        = (const float*)d_in[4];
    const float* b0        = (const float*)d_in[5];
    const float* We1       = (const float*)d_in[6];
    const float* be1       = (const float*)d_in[7];
    const float* We2       = (const float*)d_in[8];
    const float* be2       = (const float*)d_in[9];
    const float* conv_bias = (const float*)d_in[10];
    const float* gamma     = (const float*)d_in[11];
    const float* beta      = (const float*)d_in[12];
    float* out = (float*)d_out;

    cudaFuncSetAttribute(tgemm, cudaFuncAttributeMaxDynamicSharedMemorySize, TG_SMEM);

    // one-time prep
    node_mlp<<<N_NODES, 64>>>(n_feat, W0, b0, be2);
    edge_h1<<<(N_EDGES * EH) / 256, 256>>>(e_feat, We1, be1);
    wt_prep<<<(TCOLS * 64) / 256, 256>>>(We2);
    zero_bins<<<(N_NODES + 255) / 256, 256>>>();
    hist_kernel<<<(N_EDGES + 255) / 256, 256>>>(src);
    scan_kernel<<<1, 1024>>>();
    scatter_kernel<<<(N_EDGES + 255) / 256, 256>>>(src);

    int nh = N_NODES * H;
    dim3 tgrid(TCOLS / 128, (N_NODES + 127) / 128);
    for (int step = 0; step < STEPS; step++) {
        tgemm<<<tgrid, 128, TG_SMEM>>>();
        init_agg<<<(nh + 255) / 256, 256>>>(conv_bias);
        msg_kernel2<<<N_NODES, 256>>>(dst);
        if (step < STEPS - 1) {
            relu_step_b<<<N_NODES, 64>>>(be2);
        } else {
            relu_step_b<<<N_NODES, 64>>>(be2);  // x needed for BN
        }
    }

    bn_zero<<<1, 64>>>();
    bn_reduce<<<100, 256>>>();
    bn_apply<<<(nh + 255) / 256, 256>>>(gamma, beta, out);
    (void)in_sizes; (void)n_in; (void)out_size;
}

// round 10
// speedup vs baseline: 4.3700x; 1.0958x over previous
#include <cuda_runtime.h>
#include <cuda_bf16.h>
#include <cuda_fp16.h>
#include <cstdint>

#define N_NODES 10000
#define N_EDGES 100000
#define DIN 64
#define H 64
#define EIN 16
#define EH 128
#define STEPS 3
#define KC2 192
#define TCOLS 8192

// ---------------- device scratch ----------------
__device__ float g_x[N_NODES * H];
__device__ __nv_bfloat16 g_xc[N_NODES * KC2];
__device__ float g_agg[N_NODES * H];
__device__ float g_h1f[(size_t)N_EDGES * EH];
__device__ __nv_bfloat16 g_WtC[TCOLS * KC2];
__device__ __half g_T[(size_t)N_NODES * TCOLS];
__device__ float g_B[N_NODES * H];
__device__ int g_cnt[N_NODES];
__device__ int g_fill[N_NODES];
__device__ int g_rowptr[N_NODES + 1];
__device__ int g_eidx[N_EDGES];
__device__ float g_sum[H];
__device__ float g_sumsq[H];

// ---------------- helpers ----------------
__device__ __forceinline__ uint32_t smem_u32(const void* p) {
    uint32_t a;
    asm("{ .reg .u64 t; cvta.to.shared.u64 t, %1; cvt.u32.u64 %0, t; }" : "=r"(a) : "l"(p));
    return a;
}
__device__ __forceinline__ void cp_async16(uint32_t dst, const void* src, int src_bytes) {
    asm volatile("cp.async.cg.shared.global [%0], [%1], 16, %2;"
                 :: "r"(dst), "l"(src), "r"(src_bytes));
}
#define CP_COMMIT() asm volatile("cp.async.commit_group;" ::: "memory")
#define CP_WAIT(n)  asm volatile("cp.async.wait_group %0;" :: "n"(n) : "memory")

__device__ __forceinline__ void ldsm_x4(uint32_t& r0, uint32_t& r1, uint32_t& r2,
                                        uint32_t& r3, uint32_t addr) {
    asm volatile("ldmatrix.sync.aligned.m8n8.x4.shared.b16 {%0,%1,%2,%3}, [%4];"
                 : "=r"(r0), "=r"(r1), "=r"(r2), "=r"(r3) : "r"(addr));
}
__device__ __forceinline__ void mma_bf16(float& c0, float& c1, float& c2, float& c3,
                                         uint32_t a0, uint32_t a1, uint32_t a2, uint32_t a3,
                                         uint32_t b0, uint32_t b1) {
    asm volatile(
        "mma.sync.aligned.m16n8k16.row.col.f32.bf16.bf16.f32 "
        "{%0,%1,%2,%3}, {%4,%5,%6,%7}, {%8,%9}, {%0,%1,%2,%3};"
        : "+f"(c0), "+f"(c1), "+f"(c2), "+f"(c3)
        : "r"(a0), "r"(a1), "r"(a2), "r"(a3), "r"(b0), "r"(b1));
}
__device__ __forceinline__ void split_store(float v, __nv_bfloat16* row, int j) {
    __nv_bfloat16 hi = __float2bfloat16(v);
    __nv_bfloat16 lo = __float2bfloat16(v - __bfloat162float(hi));
    row[j] = hi;
    row[64 + j] = hi;
    row[128 + j] = lo;
}

// ---------------- node MLP (x, x-split, B for step 0, agg init) ----------------
__global__ void node_mlp(const float* __restrict__ nf, const float* __restrict__ W0,
                         const float* __restrict__ b0, const float* __restrict__ be2,
                         const float* __restrict__ conv_bias) {
    int n = blockIdx.x;
    int h = threadIdx.x;
    __shared__ float xs[DIN];
    __shared__ float vs[64];
    xs[h] = nf[n * DIN + h];
    __syncthreads();
    float acc = b0[h];
#pragma unroll
    for (int i = 0; i < DIN; i++) acc += xs[i] * W0[i * H + h];
    float v = fmaxf(acc, 0.0f);
    g_x[n * H + h] = v;
    split_store(v, g_xc + n * KC2, h);
    g_agg[n * H + h] = conv_bias[h];
    vs[h] = v;
    __syncthreads();
    float accB = 0.f;
#pragma unroll
    for (int j = 0; j < 64; j++) accB += vs[j] * be2[j * 64 + h];
    g_B[n * 64 + h] = accB;
}

// ---------------- edge hidden (fp32) ----------------
__global__ void edge_h1(const float* __restrict__ ef, const float* __restrict__ We1,
                        const float* __restrict__ be1) {
    int gid = blockIdx.x * blockDim.x + threadIdx.x;
    int e = gid >> 7;
    int k = gid & 127;
    if (e >= N_EDGES) return;
    float acc = be1[k];
#pragma unroll
    for (int i = 0; i < EIN; i++) acc += ef[e * EIN + i] * We1[i * EH + k];
    g_h1f[gid] = fmaxf(acc, 0.0f);
}

// ---------------- W' prep ----------------
__global__ void wt_prep(const float* __restrict__ We2) {
    int idx = blockIdx.x * blockDim.x + threadIdx.x;
    if (idx >= TCOLS * 64) return;
    int col = idx >> 6;
    int j = idx & 63;
    int k = col >> 6;
    int o = col & 63;
    float v = We2[k * 4096 + j * 64 + o];
    __nv_bfloat16 hi = __float2bfloat16(v);
    __nv_bfloat16 lo = __float2bfloat16(v - __bfloat162float(hi));
    __nv_bfloat16* row = g_WtC + col * KC2;
    row[j] = hi;
    row[64 + j] = lo;
    row[128 + j] = hi;
}

// ---------------- edge sort by src ----------------
__global__ void zero_bins() {
    int i = blockIdx.x * blockDim.x + threadIdx.x;
    if (i < N_NODES) { g_cnt[i] = 0; g_fill[i] = 0; }
}
__global__ void hist_kernel(const int* __restrict__ src) {
    int e = blockIdx.x * blockDim.x + threadIdx.x;
    if (e < N_EDGES) atomicAdd(&g_cnt[src[e]], 1);
}
__global__ void scan_kernel() {
    __shared__ int ts[1024];
    int t = threadIdx.x;
    int base = t * 10;
    int c[10];
    int tot = 0;
#pragma unroll
    for (int i = 0; i < 10; i++) {
        int idx = base + i;
        c[i] = (idx < N_NODES) ? g_cnt[idx] : 0;
        tot += c[i];
    }
    ts[t] = tot;
    __syncthreads();
    for (int off = 1; off < 1024; off <<= 1) {
        int v = (t >= off) ? ts[t - off] : 0;
        __syncthreads();
        ts[t] += v;
        __syncthreads();
    }
    int run = ts[t] - tot;
#pragma unroll
    for (int i = 0; i < 10; i++) {
        int idx = base + i;
        if (idx < N_NODES) { g_rowptr[idx] = run; run += c[i]; }
    }
    if (t == 1023) g_rowptr[N_NODES] = N_EDGES;
}
__global__ void scatter_kernel(const int* __restrict__ src) {
    int e = blockIdx.x * blockDim.x + threadIdx.x;
    if (e >= N_EDGES) return;
    int s = src[e];
    int pos = g_rowptr[s] + atomicAdd(&g_fill[s], 1);
    g_eidx[pos] = e;
}

// ---------------- T-GEMM ----------------
#define BKT 64
#define STAGE_BYTES 32768
#define TG_SMEM (3 * STAGE_BYTES)
#define NKT2 3

__global__ void __launch_bounds__(128, 2) tgemm() {
    extern __shared__ char smem[];
    const uint32_t sbase = smem_u32(smem);
    const int tid = threadIdx.x;
    const int wid = tid >> 5;
    const int lane = tid & 31;
    const int block_n = blockIdx.x * 128;
    const int block_m = blockIdx.y * 128;

    const int wm = wid & 1;
    const int wn = wid >> 1;
    const int m_off = wm * 64;
    const int n_off = wn * 64;

    float acc[4][8][4];
#pragma unroll
    for (int mt = 0; mt < 4; mt++)
#pragma unroll
        for (int nt = 0; nt < 8; nt++)
#pragma unroll
            for (int q = 0; q < 4; q++) acc[mt][nt][q] = 0.0f;

    auto load_stage = [&](int stage, int kt) {
        const int k0 = kt * BKT;
        const uint32_t As = sbase + stage * STAGE_BYTES;
        const uint32_t Bs = As + 16384;
#pragma unroll
        for (int i = 0; i < 8; i++) {
            int cid = tid + i * 128;
            int r = cid >> 3;
            int c = cid & 7;
            int n = block_m + r;
            const void* gsrc = g_xc + (size_t)n * KC2 + k0 + c * 8;
            uint32_t sdst = As + r * 128 + ((c ^ (r & 7)) << 4);
            cp_async16(sdst, gsrc, (n < N_NODES) ? 16 : 0);
        }
#pragma unroll
        for (int i = 0; i < 8; i++) {
            int cid = tid + i * 128;
            int r = cid >> 3;
            int c = cid & 7;
            int col = block_n + r;
            const void* gsrc = g_WtC + (size_t)col * KC2 + k0 + c * 8;
            uint32_t sdst = Bs + r * 128 + ((c ^ (r & 7)) << 4);
            cp_async16(sdst, gsrc, 16);
        }
    };

    const int a_row_l = lane & 15;
    const int a_uoff = lane >> 4;
    const int b_row_l = ((lane >> 4) << 3) + (lane & 7);
    const int b_uoff = (lane >> 3) & 1;

    load_stage(0, 0);
    CP_COMMIT();
    load_stage(1, 1);
    CP_COMMIT();

#pragma unroll
    for (int kt = 0; kt < NKT2; kt++) {
        if (kt == NKT2 - 1) { CP_WAIT(0); } else { CP_WAIT(1); }
        __syncthreads();
        if (kt + 2 < NKT2) {
            load_stage(kt + 2, kt + 2);
            CP_COMMIT();
        }
        const uint32_t As = sbase + kt * STAGE_BYTES;
        const uint32_t Bs = As + 16384;
#pragma unroll
        for (int ks = 0; ks < 4; ks++) {
            const int ub = ks * 2;
            uint32_t a[4][4];
#pragma unroll
            for (int mt = 0; mt < 4; mt++) {
                int r = m_off + mt * 16 + a_row_l;
                int u = ub + a_uoff;
                ldsm_x4(a[mt][0], a[mt][1], a[mt][2], a[mt][3],
                        As + r * 128 + ((u ^ (r & 7)) << 4));
            }
            uint32_t b[8][2];
#pragma unroll
            for (int np = 0; np < 4; np++) {
                int r = n_off + np * 16 + b_row_l;
                int u = ub + b_uoff;
                uint32_t r0, r1, r2, r3;
                ldsm_x4(r0, r1, r2, r3, Bs + r * 128 + ((u ^ (r & 7)) << 4));
                b[np * 2][0] = r0; b[np * 2][1] = r1;
                b[np * 2 + 1][0] = r2; b[np * 2 + 1][1] = r3;
            }
#pragma unroll
            for (int mt = 0; mt < 4; mt++)
#pragma unroll
                for (int nt = 0; nt < 8; nt++)
                    mma_bf16(acc[mt][nt][0], acc[mt][nt][1], acc[mt][nt][2], acc[mt][nt][3],
                             a[mt][0], a[mt][1], a[mt][2], a[mt][3],
                             b[nt][0], b[nt][1]);
        }
        __syncthreads();
    }

    const int qrow = lane >> 2;
    const int qcol = (lane & 3) * 2;
#pragma unroll
    for (int mt = 0; mt < 4; mt++) {
        int r0 = block_m + m_off + mt * 16 + qrow;
        int r1 = r0 + 8;
#pragma unroll
        for (int nt = 0; nt < 8; nt++) {
            int col = block_n + n_off + nt * 8 + qcol;
            if (r0 < N_NODES)
                *(__half2*)(g_T + (size_t)r0 * TCOLS + col) =
                    __floats2half2_rn(acc[mt][nt][0], acc[mt][nt][1]);
            if (r1 < N_NODES)
                *(__half2*)(g_T + (size_t)r1 * TCOLS + col) =
                    __floats2half2_rn(acc[mt][nt][2], acc[mt][nt][3]);
        }
    }
}

// ---------------- msg: CTA per src, 4 edges/warp, smem h-stage (no shuffles) ----------------
__global__ void __launch_bounds__(256) msg_kernel2(const int* __restrict__ dst) {
    int s = blockIdx.x;
    int beg = g_rowptr[s];
    int end = g_rowptr[s + 1];
    if (beg == end) return;
    __shared__ float Ts[TCOLS];              // 32 KB
    __shared__ float hst[8][4][128];         // 16 KB  (total 48 KB static)
    int tid = threadIdx.x;
    const uint4* Trow4 = (const uint4*)(g_T + (size_t)s * TCOLS);
    float4* Ts4 = (float4*)Ts;
#pragma unroll
    for (int i = 0; i < 4; i++) {
        int idx = tid + i * 256;
        uint4 v = Trow4[idx];
        const __half2* hp = (const __half2*)&v;
        float2 f0 = __half22float2(hp[0]);
        float2 f1 = __half22float2(hp[1]);
        float2 f2 = __half22float2(hp[2]);
        float2 f3 = __half22float2(hp[3]);
        Ts4[idx * 2 + 0] = make_float4(f0.x, f0.y, f1.x, f1.y);
        Ts4[idx * 2 + 1] = make_float4(f2.x, f2.y, f3.x, f3.y);
    }
    __syncthreads();

    int wid = tid >> 5;
    int lane = tid & 31;
    const float2* T2 = (const float2*)Ts;
    float b0v = g_B[s * 64 + 2 * lane];
    float b1v = g_B[s * 64 + 2 * lane + 1];

    for (int base = beg + wid * 4; base < end; base += 32) {
        int ne = end - base;
        if (ne > 4) ne = 4;
        int d[4];
        float m0[4], m1[4];
#pragma unroll
        for (int j = 0; j < 4; j++) {
            m0[j] = b0v;
            m1[j] = b1v;
            d[j] = 0;
        }
        // stage h1 rows for this warp's edges into smem
#pragma unroll
        for (int j = 0; j < 4; j++) {
            if (j < ne) {
                int e = g_eidx[base + j];
                d[j] = dst[e];
                float4 hv = *(const float4*)(g_h1f + (size_t)e * EH + lane * 4);
                *(float4*)&hst[wid][j][lane * 4] = hv;
            }
        }
        __syncwarp();
#pragma unroll 4
        for (int kb = 0; kb < 32; kb++) {
            float2 t0 = T2[(kb * 4 + 0) * 32 + lane];
            float2 t1 = T2[(kb * 4 + 1) * 32 + lane];
            float2 t2 = T2[(kb * 4 + 2) * 32 + lane];
            float2 t3 = T2[(kb * 4 + 3) * 32 + lane];
#pragma unroll
            for (int j = 0; j < 4; j++) {
                float4 h = *(const float4*)&hst[wid][j][kb * 4];  // broadcast
                m0[j] = fmaf(h.x, t0.x, m0[j]);
                m1[j] = fmaf(h.x, t0.y, m1[j]);
                m0[j] = fmaf(h.y, t1.x, m0[j]);
                m1[j] = fmaf(h.y, t1.y, m1[j]);
                m0[j] = fmaf(h.z, t2.x, m0[j]);
                m1[j] = fmaf(h.z, t2.y, m1[j]);
                m0[j] = fmaf(h.w, t3.x, m0[j]);
                m1[j] = fmaf(h.w, t3.y, m1[j]);
            }
        }
#pragma unroll
        for (int j = 0; j < 4; j++) {
            if (j < ne) {
                atomicAdd(&g_agg[d[j] * H + 2 * lane], m0[j]);
                atomicAdd(&g_agg[d[j] * H + 2 * lane + 1], m1[j]);
            }
        }
        __syncwarp();
    }
}

// ---------------- relu step (x, x-split, B; re-init agg) ----------------
__global__ void relu_step_b(const float* __restrict__ be2,
                            const float* __restrict__ conv_bias) {
    int n = blockIdx.x;
    int o = threadIdx.x;
    __shared__ float xs[64];
    float v = fmaxf(g_agg[n * 64 + o], 0.0f);
    g_x[n * 64 + o] = v;
    split_store(v, g_xc + n * KC2, o);
    g_agg[n * 64 + o] = conv_bias[o];
    xs[o] = v;
    __syncthreads();
    float acc = 0.f;
#pragma unroll
    for (int j = 0; j < 64; j++) acc += xs[j] * be2[j * 64 + o];
    g_B[n * 64 + o] = acc;
}

// ---------------- BatchNorm ----------------
__global__ void bn_zero() {
    int t = threadIdx.x;
    if (t < H) { g_sum[t] = 0.f; g_sumsq[t] = 0.f; }
}
__global__ void bn_reduce() {
    int t = threadIdx.x;
    int h = t & 63;
    int rsub = t >> 6;
    float s = 0.f, q = 0.f;
    for (int r = blockIdx.x * 4 + rsub; r < N_NODES; r += gridDim.x * 4) {
        float v = g_x[r * H + h];
        s += v;
        q += v * v;
    }
    __shared__ float ss[256], sq[256];
    ss[t] = s;
    sq[t] = q;
    __syncthreads();
    if (t < 64) {
        s = ss[t] + ss[t + 64] + ss[t + 128] + ss[t + 192];
        q = sq[t] + sq[t + 64] + sq[t + 128] + sq[t + 192];
        atomicAdd(&g_sum[h], s);
        atomicAdd(&g_sumsq[h], q);
    }
}
__global__ void bn_apply(const float* __restrict__ gamma, const float* __restrict__ beta,
                         float* __restrict__ out) {
    int i = blockIdx.x * blockDim.x + threadIdx.x;
    if (i >= N_NODES * H) return;
    int h = i & 63;
    float mean = g_sum[h] / (float)N_NODES;
    float var = g_sumsq[h] / (float)N_NODES - mean * mean;
    out[i] = (g_x[i] - mean) * rsqrtf(var + 1e-5f) * gamma[h] + beta[h];
}

// ---------------- launch ----------------
extern "C" void kernel_launch(void* const* d_in, const int* in_sizes, int n_in,
                              void* d_out, int out_size) {
    const float* n_feat    = (const float*)d_in[0];
    const float* e_feat    = (const float*)d_in[1];
    const int*   src       = (const int*)d_in[2];
    const int*   dst       = (const int*)d_in[3];
    const float* W0        = (const float*)d_in[4];
    const float* b0        = (const float*)d_in[5];
    const float* We1       = (const float*)d_in[6];
    const float* be1       = (const float*)d_in[7];
    const float* We2       = (const float*)d_in[8];
    const float* be2       = (const float*)d_in[9];
    const float* conv_bias = (const float*)d_in[10];
    const float* gamma     = (const float*)d_in[11];
    const float* beta      = (const float*)d_in[12];
    float* out = (float*)d_out;

    static cudaStream_t s_aux = nullptr;
    static cudaEvent_t ev_fork = nullptr, ev_join = nullptr;
    if (!s_aux) {
        cudaStreamCreateWithFlags(&s_aux, cudaStreamNonBlocking);
        cudaEventCreateWithFlags(&ev_fork, cudaEventDisableTiming);
        cudaEventCreateWithFlags(&ev_join, cudaEventDisableTiming);
    }

    cudaFuncSetAttribute(tgemm, cudaFuncAttributeMaxDynamicSharedMemorySize, TG_SMEM);

    // fork: edge-side prep on aux stream, node/weight prep on main
    cudaEventRecord(ev_fork, 0);
    cudaStreamWaitEvent(s_aux, ev_fork, 0);
    edge_h1<<<(N_EDGES * EH) / 256, 256, 0, s_aux>>>(e_feat, We1, be1);
    zero_bins<<<(N_NODES + 255) / 256, 256, 0, s_aux>>>();
    hist_kernel<<<(N_EDGES + 255) / 256, 256, 0, s_aux>>>(src);
    scan_kernel<<<1, 1024, 0, s_aux>>>();
    scatter_kernel<<<(N_EDGES + 255) / 256, 256, 0, s_aux>>>(src);
    cudaEventRecord(ev_join, s_aux);

    node_mlp<<<N_NODES, 64>>>(n_feat, W0, b0, be2, conv_bias);
    wt_prep<<<(TCOLS * 64) / 256, 256>>>(We2);
    cudaStreamWaitEvent(0, ev_join, 0);

    int nh = N_NODES * H;
    dim3 tgrid(TCOLS / 128, (N_NODES + 127) / 128);
    for (int step = 0; step < STEPS; step++) {
        tgemm<<<tgrid, 128, TG_SMEM>>>();
        msg_kernel2<<<N_NODES, 256>>>(dst);
        relu_step_b<<<N_NODES, 64>>>(be2, conv_bias);
    }

    bn_zero<<<1, 64>>>();
    bn_reduce<<<100, 256>>>();
    bn_apply<<<(nh + 255) / 256, 256>>>(gamma, beta, out);
    (void)in_sizes; (void)n_in; (void)out_size;
}